// round 13
// baseline (speedup 1.0000x reference)
#include <cuda_runtime.h>
#include <cuda_bf16.h>
#include <math_constants.h>
#include <cstdint>

#define NB   1024
#define NH   16384
#define SDIM 32
#define HID  64
#define NK   4
#define GA   80

#define MQ   256
#define KT   128
#define NSPLIT 8
#define KEYS_PER_CTA (NH / NSPLIT)   // 2048
#define TILES (KEYS_PER_CTA / KT)    // 16
#define ATHR 512

#define KROWB 144    // K/Q smem row stride bytes (64 bf16 + 16B pad)
#define VROWB 272    // V smem row stride bytes (128 bf16 + 16B pad)

// attn smem byte offsets
#define SM_MHAT 0                            // 256 floats
#define SM_QLO  1024                         // 256 * KROWB = 36864
#define SM_KH0  (SM_QLO + 256 * KROWB)       // 37888
#define SM_QHI  SM_KH0                       // Q-hi staging aliases KH0+KL0 (256 rows)
#define SM_KL0  (SM_KH0 + 128 * KROWB)       // 56320
#define SM_KH1  (SM_KL0 + 128 * KROWB)       // 74752
#define SM_KL1  (SM_KH1 + 128 * KROWB)       // 93184
#define SM_VH0  (SM_KL1 + 128 * KROWB)       // 111616
#define SM_VL0  (SM_VH0 + 80 * VROWB)        // 133376
#define SM_VH1  (SM_VL0 + 80 * VROWB)        // 155136
#define SM_VL1  (SM_VH1 + 80 * VROWB)        // 176896
#define SM_TOTAL (SM_VL1 + 80 * VROWB)       // 198656

// encoder_k smem byte offsets
#define EROWB 144
#define E_XH  0
#define E_XL  18432
#define E_WH  36864
#define E_WL  46080
#define E_TOTAL 55296

// global scratch
__device__ float         g_enc_s[NK * NB * HID];
__device__ __nv_bfloat16 g_Khi[NK * NH * HID];
__device__ __nv_bfloat16 g_Klo[NK * NH * HID];
__device__ __nv_bfloat16 g_VThi[GA * NH];
__device__ __nv_bfloat16 g_VTlo[GA * NH];
__device__ float         g_Kmax[NK];
__device__ float         g_Opart[NSPLIT * NK * NB * GA];
__device__ float         g_lsum[NSPLIT * NK * NB];
// transposed + bf16-split weights [k][out][in]
__device__ __nv_bfloat16 g_W0Thi[NK * HID * SDIM];
__device__ __nv_bfloat16 g_W0Tlo[NK * HID * SDIM];
__device__ __nv_bfloat16 g_W1Thi[NK * HID * HID];
__device__ __nv_bfloat16 g_W1Tlo[NK * HID * HID];
__device__ __nv_bfloat16 g_W2Thi[NK * HID * HID];
__device__ __nv_bfloat16 g_W2Tlo[NK * HID * HID];

// ---------------- helpers ----------------
__device__ __forceinline__ float2 ffma2(float2 a, float2 b, float2 c) {
    unsigned long long ua = *reinterpret_cast<unsigned long long*>(&a);
    unsigned long long ub = *reinterpret_cast<unsigned long long*>(&b);
    unsigned long long uc = *reinterpret_cast<unsigned long long*>(&c);
    unsigned long long ud;
    asm("fma.rn.f32x2 %0, %1, %2, %3;" : "=l"(ud) : "l"(ua), "l"(ub), "l"(uc));
    return *reinterpret_cast<float2*>(&ud);
}
__device__ __forceinline__ void cp16(uint32_t sdst, const void* gsrc) {
    asm volatile("cp.async.cg.shared.global [%0], [%1], 16;" :: "r"(sdst), "l"(gsrc));
}
#define CP_COMMIT() asm volatile("cp.async.commit_group;" ::: "memory")
#define CP_WAIT(n)  asm volatile("cp.async.wait_group %0;" :: "n"(n) : "memory")

__device__ __forceinline__ void ldsm4(uint32_t* r, uint32_t addr) {
    asm volatile("ldmatrix.sync.aligned.m8n8.x4.shared.b16 {%0,%1,%2,%3}, [%4];"
        : "=r"(r[0]), "=r"(r[1]), "=r"(r[2]), "=r"(r[3]) : "r"(addr));
}
__device__ __forceinline__ void mma16816(float* d, const uint32_t* a,
                                         uint32_t b0, uint32_t b1) {
    asm volatile("mma.sync.aligned.m16n8k16.row.col.f32.bf16.bf16.f32 "
        "{%0,%1,%2,%3}, {%4,%5,%6,%7}, {%8,%9}, {%0,%1,%2,%3};"
        : "+f"(d[0]), "+f"(d[1]), "+f"(d[2]), "+f"(d[3])
        : "r"(a[0]), "r"(a[1]), "r"(a[2]), "r"(a[3]), "r"(b0), "r"(b1));
}
__device__ __forceinline__ uint32_t packbf(float hi, float lo) {
    uint32_t r;
    asm("cvt.rn.bf16x2.f32 %0, %1, %2;" : "=r"(r) : "f"(hi), "f"(lo));
    return r;
}

// ---------------------------------------------------------------------------
// Weight prep: transpose to [k][out][in] and bf16 hi/lo split.
// ---------------------------------------------------------------------------
__global__ __launch_bounds__(256) void wprep_kernel(
    const float* __restrict__ W0, const float* __restrict__ W1,
    const float* __restrict__ W2)
{
    int idx = blockIdx.x * 256 + threadIdx.x;
    float f;
    __nv_bfloat16* dh;
    __nv_bfloat16* dl;
    int d;
    if (idx < NK * HID * SDIM) {
        int k = idx / (HID * SDIM), r = idx % (HID * SDIM);
        int o = r / SDIM, i = r % SDIM;
        f = W0[((size_t)k * SDIM + i) * HID + o];
        dh = g_W0Thi; dl = g_W0Tlo; d = idx;
    } else if (idx < NK * HID * SDIM + NK * HID * HID) {
        int x = idx - NK * HID * SDIM;
        int k = x / (HID * HID), r = x % (HID * HID);
        int o = r / HID, i = r % HID;
        f = W1[((size_t)k * HID + i) * HID + o];
        dh = g_W1Thi; dl = g_W1Tlo; d = x;
    } else if (idx < NK * HID * SDIM + 2 * NK * HID * HID) {
        int x = idx - NK * HID * SDIM - NK * HID * HID;
        int k = x / (HID * HID), r = x % (HID * HID);
        int o = r / HID, i = r % HID;
        f = W2[((size_t)k * HID + i) * HID + o];
        dh = g_W2Thi; dl = g_W2Tlo; d = x;
    } else return;
    __nv_bfloat16 h = __float2bfloat16(f);
    dh[d] = h;
    dl[d] = __float2bfloat16(f - __bfloat162float(h));
}

// ---------------------------------------------------------------------------
// History encoder on tensor cores: 3x (Linear+ReLU), 3-pass bf16 error-split.
// Grid (NH/128, NK), 256 threads (8 warps x 16 rows). Emits g_Khi/g_Klo +
// per-k max row norm (g_Kmax).
// ---------------------------------------------------------------------------
__global__ __launch_bounds__(256) void encoder_k_kernel(
    const float* __restrict__ x,
    const float* __restrict__ b0, const float* __restrict__ b1,
    const float* __restrict__ b2)
{
    extern __shared__ char esm[];
    const uint32_t sb = (uint32_t)__cvta_generic_to_shared(esm);
    const int tid  = threadIdx.x;
    const int warp = tid >> 5;
    const int lane = tid & 31;
    const int k    = blockIdx.y;
    const int row0 = blockIdx.x * 128;

    // X0: 128 rows x 32 cols fp32 -> bf16 hi/lo smem
    #pragma unroll
    for (int it = 0; it < 16; it++) {
        int idx = tid + it * 256;
        int row = idx >> 5, c = idx & 31;
        float f = x[(size_t)(row0 + row) * SDIM + c];
        __nv_bfloat16 h = __float2bfloat16(f);
        *(__nv_bfloat16*)(esm + E_XH + row * EROWB + c * 2) = h;
        *(__nv_bfloat16*)(esm + E_XL + row * EROWB + c * 2) =
            __float2bfloat16(f - __bfloat162float(h));
    }
    // W0T: 64 rows x 32 bf16 (64B) via cp.async
    {
        int row = tid >> 2, c = tid & 3;
        cp16(sb + E_WH + row * EROWB + c * 16,
             g_W0Thi + ((size_t)k * HID + row) * SDIM + c * 8);
        cp16(sb + E_WL + row * EROWB + c * 16,
             g_W0Tlo + ((size_t)k * HID + row) * SDIM + c * 8);
    }
    CP_COMMIT();
    CP_WAIT(0);
    __syncthreads();

    const uint32_t aro  = (16 * warp + (lane & 15)) * EROWB;
    const uint32_t asel = ((lane >> 4) & 1) * 8;
    const uint32_t lr8  = lane & 7, lc8 = (lane >> 3) & 3;
    const int r = lane >> 2, tq = lane & 3;
    const int wrow = 16 * warp + r;

    float acc[8][4];

    // ---- layer 0 (K=32) ----
    #pragma unroll
    for (int n = 0; n < 8; n++)
        #pragma unroll
        for (int e = 0; e < 4; e++) acc[n][e] = 0.f;
    {
        uint32_t ah[2][4], al[2][4];
        #pragma unroll
        for (int kf = 0; kf < 2; kf++) {
            ldsm4(ah[kf], sb + E_XH + aro + (kf * 16 + asel) * 2);
            ldsm4(al[kf], sb + E_XL + aro + (kf * 16 + asel) * 2);
        }
        const uint32_t co = (lc8 * 8) * 2;
        #pragma unroll
        for (int n = 0; n < 8; n++) {
            uint32_t bh[4], bl[4];
            ldsm4(bh, sb + E_WH + (n * 8 + lr8) * EROWB + co);
            ldsm4(bl, sb + E_WL + (n * 8 + lr8) * EROWB + co);
            mma16816(acc[n], ah[0], bh[0], bh[1]);
            mma16816(acc[n], ah[1], bh[2], bh[3]);
            mma16816(acc[n], al[0], bh[0], bh[1]);
            mma16816(acc[n], al[1], bh[2], bh[3]);
            mma16816(acc[n], ah[0], bl[0], bl[1]);
            mma16816(acc[n], ah[1], bl[2], bl[3]);
        }
    }
    __syncthreads();   // all layer-0 reads complete

    // bias+ReLU+split -> X smem; load W1
    {
        const float* bp = b0 + k * HID;
        #pragma unroll
        for (int n = 0; n < 8; n++) {
            int col = n * 8 + tq * 2;
            float ba = __ldg(bp + col), bb = __ldg(bp + col + 1);
            float h0 = fmaxf(acc[n][0] + ba, 0.f);
            float h1 = fmaxf(acc[n][1] + bb, 0.f);
            float h2 = fmaxf(acc[n][2] + ba, 0.f);
            float h3 = fmaxf(acc[n][3] + bb, 0.f);
            uint32_t w01 = packbf(h1, h0), w23 = packbf(h3, h2);
            float r0 = h0 - __uint_as_float(w01 << 16);
            float r1 = h1 - __uint_as_float(w01 & 0xffff0000u);
            float r2 = h2 - __uint_as_float(w23 << 16);
            float r3 = h3 - __uint_as_float(w23 & 0xffff0000u);
            *(uint32_t*)(esm + E_XH + wrow * EROWB + col * 2)       = w01;
            *(uint32_t*)(esm + E_XH + (wrow + 8) * EROWB + col * 2) = w23;
            *(uint32_t*)(esm + E_XL + wrow * EROWB + col * 2)       = packbf(r1, r0);
            *(uint32_t*)(esm + E_XL + (wrow + 8) * EROWB + col * 2) = packbf(r3, r2);
        }
        #pragma unroll
        for (int it = 0; it < 2; it++) {
            int idx = tid + it * 256;
            int row = idx >> 3, c = idx & 7;
            cp16(sb + E_WH + row * EROWB + c * 16,
                 g_W1Thi + ((size_t)k * HID + row) * HID + c * 8);
            cp16(sb + E_WL + row * EROWB + c * 16,
                 g_W1Tlo + ((size_t)k * HID + row) * HID + c * 8);
        }
        CP_COMMIT();
        CP_WAIT(0);
        __syncthreads();
    }

    // ---- layers 1 & 2 (K=64) ----
    #pragma unroll
    for (int layer = 1; layer <= 2; layer++) {
        #pragma unroll
        for (int n = 0; n < 8; n++)
            #pragma unroll
            for (int e = 0; e < 4; e++) acc[n][e] = 0.f;
        uint32_t ah[4][4], al[4][4];
        #pragma unroll
        for (int kf = 0; kf < 4; kf++) {
            ldsm4(ah[kf], sb + E_XH + aro + (kf * 16 + asel) * 2);
            ldsm4(al[kf], sb + E_XL + aro + (kf * 16 + asel) * 2);
        }
        #pragma unroll
        for (int dp = 0; dp < 2; dp++) {
            const uint32_t co = (dp * 32 + lc8 * 8) * 2;
            const int k0 = 2 * dp, k1 = 2 * dp + 1;
            #pragma unroll
            for (int n = 0; n < 8; n++) {
                uint32_t bh[4], bl[4];
                ldsm4(bh, sb + E_WH + (n * 8 + lr8) * EROWB + co);
                ldsm4(bl, sb + E_WL + (n * 8 + lr8) * EROWB + co);
                mma16816(acc[n], ah[k0], bh[0], bh[1]);
                mma16816(acc[n], ah[k1], bh[2], bh[3]);
                mma16816(acc[n], al[k0], bh[0], bh[1]);
                mma16816(acc[n], al[k1], bh[2], bh[3]);
                mma16816(acc[n], ah[k0], bl[0], bl[1]);
                mma16816(acc[n], ah[k1], bl[2], bl[3]);
            }
        }
        __syncthreads();

        if (layer == 1) {
            const float* bp = b1 + k * HID;
            #pragma unroll
            for (int n = 0; n < 8; n++) {
                int col = n * 8 + tq * 2;
                float ba = __ldg(bp + col), bb = __ldg(bp + col + 1);
                float h0 = fmaxf(acc[n][0] + ba, 0.f);
                float h1 = fmaxf(acc[n][1] + bb, 0.f);
                float h2 = fmaxf(acc[n][2] + ba, 0.f);
                float h3 = fmaxf(acc[n][3] + bb, 0.f);
                uint32_t w01 = packbf(h1, h0), w23 = packbf(h3, h2);
                float r0 = h0 - __uint_as_float(w01 << 16);
                float r1 = h1 - __uint_as_float(w01 & 0xffff0000u);
                float r2 = h2 - __uint_as_float(w23 << 16);
                float r3 = h3 - __uint_as_float(w23 & 0xffff0000u);
                *(uint32_t*)(esm + E_XH + wrow * EROWB + col * 2)       = w01;
                *(uint32_t*)(esm + E_XH + (wrow + 8) * EROWB + col * 2) = w23;
                *(uint32_t*)(esm + E_XL + wrow * EROWB + col * 2)       = packbf(r1, r0);
                *(uint32_t*)(esm + E_XL + (wrow + 8) * EROWB + col * 2) = packbf(r3, r2);
            }
            #pragma unroll
            for (int it = 0; it < 2; it++) {
                int idx = tid + it * 256;
                int row = idx >> 3, c = idx & 7;
                cp16(sb + E_WH + row * EROWB + c * 16,
                     g_W2Thi + ((size_t)k * HID + row) * HID + c * 8);
                cp16(sb + E_WL + row * EROWB + c * 16,
                     g_W2Tlo + ((size_t)k * HID + row) * HID + c * 8);
            }
            CP_COMMIT();
            CP_WAIT(0);
            __syncthreads();
        } else {
            // final: write g_Khi/g_Klo + row norms
            const float* bp = b2 + k * HID;
            const size_t ga = (size_t)k * NH + row0 + wrow;
            float sA = 0.f, sB = 0.f;
            #pragma unroll
            for (int n = 0; n < 8; n++) {
                int col = n * 8 + tq * 2;
                float ba = __ldg(bp + col), bb = __ldg(bp + col + 1);
                float h0 = fmaxf(acc[n][0] + ba, 0.f);
                float h1 = fmaxf(acc[n][1] + bb, 0.f);
                float h2 = fmaxf(acc[n][2] + ba, 0.f);
                float h3 = fmaxf(acc[n][3] + bb, 0.f);
                sA += h0 * h0 + h1 * h1;
                sB += h2 * h2 + h3 * h3;
                uint32_t w01 = packbf(h1, h0), w23 = packbf(h3, h2);
                float r0 = h0 - __uint_as_float(w01 << 16);
                float r1 = h1 - __uint_as_float(w01 & 0xffff0000u);
                float r2 = h2 - __uint_as_float(w23 << 16);
                float r3 = h3 - __uint_as_float(w23 & 0xffff0000u);
                *(uint32_t*)((__nv_bfloat16*)g_Khi + ga * HID + col)       = w01;
                *(uint32_t*)((__nv_bfloat16*)g_Khi + (ga + 8) * HID + col) = w23;
                *(uint32_t*)((__nv_bfloat16*)g_Klo + ga * HID + col)       = packbf(r1, r0);
                *(uint32_t*)((__nv_bfloat16*)g_Klo + (ga + 8) * HID + col) = packbf(r3, r2);
            }
            sA += __shfl_xor_sync(0xffffffffu, sA, 1);
            sA += __shfl_xor_sync(0xffffffffu, sA, 2);
            sB += __shfl_xor_sync(0xffffffffu, sB, 1);
            sB += __shfl_xor_sync(0xffffffffu, sB, 2);
            if (tq == 0) {
                float mx = fmaxf(sqrtf(sA), sqrtf(sB));
                atomicMax((int*)&g_Kmax[k], __float_as_int(mx));
            }
        }
    }
}

// ---------------------------------------------------------------------------
// State encoder (SIMT fp32, small): -> g_enc_s
// ---------------------------------------------------------------------------
__global__ __launch_bounds__(256) void encoder_kernel(
    const float* __restrict__ x, int nrows,
    const float* __restrict__ W0, const float* __restrict__ b0,
    const float* __restrict__ W1, const float* __restrict__ b1,
    const float* __restrict__ W2, const float* __restrict__ b2)
{
    const int k    = blockIdx.y;
    const int row0 = blockIdx.x * 64;
    const int tid  = threadIdx.x;
    const int o    = tid & 63;
    const int rr   = tid >> 6;

    __shared__ float smem[10304];
    float* xs  = smem;
    float* hs0 = smem + 2048;
    float* hs1 = smem + 6144;
    float* hs2 = smem;   // 64*65, aliases xs+hs0 (dead by layer 2)

    for (int i = tid; i < 64 * SDIM; i += 256)
        xs[i] = x[(size_t)row0 * SDIM + i];
    __syncthreads();

    {
        float2 w[SDIM / 2];
        const float* Wp = W0 + (size_t)k * SDIM * HID + o;
        #pragma unroll
        for (int i = 0; i < SDIM / 2; i++)
            w[i] = make_float2(Wp[(2 * i) * HID], Wp[(2 * i + 1) * HID]);
        const float bias = b0[k * HID + o];
        #pragma unroll 4
        for (int r = rr; r < 64; r += 4) {
            const float2* xr = reinterpret_cast<const float2*>(xs + r * SDIM);
            float2 acc = make_float2(0.f, 0.f);
            #pragma unroll
            for (int i = 0; i < SDIM / 2; i++) acc = ffma2(xr[i], w[i], acc);
            hs0[r * HID + o] = fmaxf(acc.x + acc.y + bias, 0.f);
        }
    }
    __syncthreads();
    {
        float2 w[HID / 2];
        const float* Wp = W1 + (size_t)k * HID * HID + o;
        #pragma unroll
        for (int i = 0; i < HID / 2; i++)
            w[i] = make_float2(Wp[(2 * i) * HID], Wp[(2 * i + 1) * HID]);
        const float bias = b1[k * HID + o];
        #pragma unroll 4
        for (int r = rr; r < 64; r += 4) {
            const float2* hr = reinterpret_cast<const float2*>(hs0 + r * HID);
            float2 acc = make_float2(0.f, 0.f);
            #pragma unroll
            for (int i = 0; i < HID / 2; i++) acc = ffma2(hr[i], w[i], acc);
            hs1[r * HID + o] = fmaxf(acc.x + acc.y + bias, 0.f);
        }
    }
    __syncthreads();
    {
        float2 w[HID / 2];
        const float* Wp = W2 + (size_t)k * HID * HID + o;
        #pragma unroll
        for (int i = 0; i < HID / 2; i++)
            w[i] = make_float2(Wp[(2 * i) * HID], Wp[(2 * i + 1) * HID]);
        const float bias = b2[k * HID + o];
        #pragma unroll 4
        for (int r = rr; r < 64; r += 4) {
            const float2* hr = reinterpret_cast<const float2*>(hs1 + r * HID);
            float2 acc = make_float2(0.f, 0.f);
            #pragma unroll
            for (int i = 0; i < HID / 2; i++) acc = ffma2(hr[i], w[i], acc);
            hs2[r * 65 + o] = fmaxf(acc.x + acc.y + bias, 0.f);
        }
    }
    __syncthreads();

    for (int i = tid; i < 64 * 64; i += 256) {
        int row = i >> 6, d = i & 63;
        g_enc_s[((size_t)k * NB + row0 + row) * HID + d] = hs2[row * 65 + d];
    }
}

// ---------------------------------------------------------------------------
// V transpose + bf16 split: g_VThi/lo[a][j] = split(V[j][a])
// ---------------------------------------------------------------------------
__global__ __launch_bounds__(256) void vtrans_kernel(const float* __restrict__ V)
{
    __shared__ float sm[128 * GA];
    const int j0 = blockIdx.x * 128;
    for (int i = threadIdx.x; i < 128 * GA; i += 256)
        sm[i] = V[(size_t)j0 * GA + i];
    __syncthreads();
    for (int i = threadIdx.x; i < 128 * GA; i += 256) {
        int a = i >> 7, j = i & 127;
        float f = sm[j * GA + a];
        __nv_bfloat16 h = __float2bfloat16(f);
        __nv_bfloat16 lo = __float2bfloat16(f - __bfloat162float(h));
        g_VThi[(size_t)a * NH + j0 + j] = h;
        g_VTlo[(size_t)a * NH + j0 + j] = lo;
    }
}

// ---------------------------------------------------------------------------
// mma.sync flash attention (unchanged from R10). Grid (4, NK, NSPLIT), 512 thr.
// ---------------------------------------------------------------------------
__device__ __forceinline__ void load_tile(uint32_t sb, int k, int key0, int buf,
                                          int tid)
{
    const uint32_t kh = sb + (buf ? SM_KH1 : SM_KH0);
    const uint32_t kl = sb + (buf ? SM_KL1 : SM_KL0);
    const char* shi = (const char*)(g_Khi + ((size_t)k * NH + key0) * HID);
    const char* slo = (const char*)(g_Klo + ((size_t)k * NH + key0) * HID);
    #pragma unroll
    for (int it = 0; it < 2; it++) {
        int idx = tid + it * ATHR;              // 0..1023
        int row = idx >> 3, c = idx & 7;
        uint32_t doff = row * KROWB + c * 16;
        size_t goff = (size_t)row * 128 + c * 16;
        cp16(kh + doff, shi + goff);
        cp16(kl + doff, slo + goff);
    }
    const uint32_t vh = sb + (buf ? SM_VH1 : SM_VH0);
    const uint32_t vl = sb + (buf ? SM_VL1 : SM_VL0);
    const char* vhi = (const char*)g_VThi + (size_t)key0 * 2;
    const char* vlo = (const char*)g_VTlo + (size_t)key0 * 2;
    #pragma unroll
    for (int it = 0; it < 3; it++) {
        int idx = tid + it * ATHR;              // 0..1535, need 1280
        if (idx < 1280) {
            int a = idx >> 4, c = idx & 15;
            uint32_t doff = a * VROWB + c * 16;
            size_t goff = (size_t)a * NH * 2 + c * 16;
            cp16(vh + doff, vhi + goff);
            cp16(vl + doff, vlo + goff);
        }
    }
}

__global__ __launch_bounds__(ATHR, 1) void attn_kernel()
{
    extern __shared__ char smem[];
    const uint32_t sb = (uint32_t)__cvta_generic_to_shared(smem);
    const int tid  = threadIdx.x;
    const int warp = tid >> 5;
    const int lane = tid & 31;
    const int k    = blockIdx.y;
    const int sp   = blockIdx.z;
    const int q0   = blockIdx.x * MQ;
    const int kb0  = sp * KEYS_PER_CTA;

    const float* Qg = g_enc_s + ((size_t)k * NB + q0) * HID;
    float* MH = (float*)(smem + SM_MHAT);

    // m-hat per query row (fixed softmax bound)
    if (tid < MQ) {
        const float4* qr = (const float4*)(Qg + tid * HID);
        float ss = 0.f;
        #pragma unroll
        for (int i = 0; i < 16; i++) {
            float4 f = qr[i];
            ss += f.x * f.x + f.y * f.y + f.z * f.z + f.w * f.w;
        }
        MH[tid] = sqrtf(ss) * g_Kmax[k];
    }

    // stage Q: hi into SM_QHI (aliases K buf0, 256 rows), lo into SM_QLO
    {
        int row = tid >> 1, half = tid & 1;
        const float* qr = Qg + row * HID + half * 32;
        char* dh = smem + SM_QHI + row * KROWB + half * 64;
        char* dl = smem + SM_QLO + row * KROWB + half * 64;
        #pragma unroll
        for (int i = 0; i < 8; i++) {
            float4 f = *(const float4*)(qr + i * 4);
            uint32_t h0 = packbf(f.y, f.x);
            uint32_t h1 = packbf(f.w, f.z);
            float r0 = f.x - __uint_as_float(h0 << 16);
            float r1 = f.y - __uint_as_float(h0 & 0xffff0000u);
            float r2 = f.z - __uint_as_float(h1 << 16);
            float r3 = f.w - __uint_as_float(h1 & 0xffff0000u);
            *(uint32_t*)(dh + i * 8)     = h0;
            *(uint32_t*)(dh + i * 8 + 4) = h1;
            *(uint32_t*)(dl + i * 8)     = packbf(r1, r0);
            *(uint32_t*)(dl + i * 8 + 4) = packbf(r3, r2);
        }
    }
    __syncthreads();

    // Q-hi fragments to registers (Q-lo stays resident in SM_QLO)
    uint32_t qh[4][4];
    const uint32_t qro = (16 * warp + (lane & 15)) * KROWB;
    const uint32_t qsel = ((lane >> 4) & 1) * 8;
    #pragma unroll
    for (int kk = 0; kk < 4; kk++)
        ldsm4(qh[kk], sb + SM_QHI + qro + (kk * 16 + qsel) * 2);
    const float mh0 = MH[16 * warp + (lane >> 2)];
    const float mh1 = MH[16 * warp + (lane >> 2) + 8];
    __syncthreads();   // Q-hi staging area now free for K tiles

    load_tile(sb, k, kb0, 0, tid);
    CP_COMMIT();

    float oacc[10][4];
    #pragma unroll
    for (int ab = 0; ab < 10; ab++)
        #pragma unroll
        for (int e = 0; e < 4; e++) oacc[ab][e] = 0.f;
    float lacc0 = 0.f, lacc1 = 0.f;

    const uint32_t lr8 = (lane & 7), lc8 = ((lane >> 3) & 3);

    for (int t = 0; t < TILES; t++) {
        if (t + 1 < TILES) {
            load_tile(sb, k, kb0 + (t + 1) * KT, (t + 1) & 1, tid);
            CP_COMMIT();
            CP_WAIT(1);
        } else {
            CP_WAIT(0);
        }
        __syncthreads();

        const uint32_t KH = sb + ((t & 1) ? SM_KH1 : SM_KH0);
        const uint32_t KL = sb + ((t & 1) ? SM_KL1 : SM_KL0);
        const uint32_t VH = sb + ((t & 1) ? SM_VH1 : SM_VH0);
        const uint32_t VL = sb + ((t & 1) ? SM_VL1 : SM_VL0);

        #pragma unroll
        for (int hf = 0; hf < 2; hf++) {
            // ---- scores for 64-key half: S = QhiKhi + QloKhi + QhiKlo ----
            float sacc[8][4];
            #pragma unroll
            for (int nb = 0; nb < 8; nb++)
                #pragma unroll
                for (int e = 0; e < 4; e++) sacc[nb][e] = 0.f;

            #pragma unroll
            for (int dp = 0; dp < 2; dp++) {
                uint32_t qlA[4], qlB[4];
                ldsm4(qlA, sb + SM_QLO + qro + ((2 * dp) * 16 + qsel) * 2);
                ldsm4(qlB, sb + SM_QLO + qro + ((2 * dp + 1) * 16 + qsel) * 2);
                const uint32_t co = (dp * 32 + lc8 * 8) * 2;
                const int k0 = 2 * dp, k1 = 2 * dp + 1;
                #pragma unroll
                for (int nb2 = 0; nb2 < 4; nb2++) {
                    const int n0 = hf * 8 + 2 * nb2, n1 = n0 + 1;
                    const int l0 = 2 * nb2, l1 = l0 + 1;
                    uint32_t bh0[4], bl0[4], bh1[4], bl1[4];
                    ldsm4(bh0, KH + (n0 * 8 + lr8) * KROWB + co);
                    ldsm4(bh1, KH + (n1 * 8 + lr8) * KROWB + co);
                    ldsm4(bl0, KL + (n0 * 8 + lr8) * KROWB + co);
                    ldsm4(bl1, KL + (n1 * 8 + lr8) * KROWB + co);
                    mma16816(sacc[l0], qh[k0], bh0[0], bh0[1]);
                    mma16816(sacc[l1], qh[k0], bh1[0], bh1[1]);
                    mma16816(sacc[l0], qh[k1], bh0[2], bh0[3]);
                    mma16816(sacc[l1], qh[k1], bh1[2], bh1[3]);
                    mma16816(sacc[l0], qlA, bh0[0], bh0[1]);
                    mma16816(sacc[l1], qlA, bh1[0], bh1[1]);
                    mma16816(sacc[l0], qlB, bh0[2], bh0[3]);
                    mma16816(sacc[l1], qlB, bh1[2], bh1[3]);
                    mma16816(sacc[l0], qh[k0], bl0[0], bl0[1]);
                    mma16816(sacc[l1], qh[k0], bl1[0], bl1[1]);
                    mma16816(sacc[l0], qh[k1], bl0[2], bl0[3]);
                    mma16816(sacc[l1], qh[k1], bl1[2], bl1[3]);
                }
            }

            // ---- softmax with fixed bound ----
            #pragma unroll
            for (int nb = 0; nb < 8; nb++) {
                float p0 = __expf(sacc[nb][0] - mh0);
                float p1 = __expf(sacc[nb][1] - mh0);
                float p2 = __expf(sacc[nb][2] - mh1);
                float p3 = __expf(sacc[nb][3] - mh1);
                lacc0 += p0 + p1;
                lacc1 += p2 + p3;
                sacc[nb][0] = p0; sacc[nb][1] = p1;
                sacc[nb][2] = p2; sacc[nb][3] = p3;
            }

            // ---- PV over this key half: O += PhiVhi + PloVhi + PhiVlo ----
            #pragma unroll
            for (int jp = 0; jp < 2; jp++) {
                uint32_t ah[2][4], al[2][4];
                #pragma unroll
                for (int m = 0; m < 2; m++) {
                    const int nA = 4 * jp + 2 * m;
                    #pragma unroll
                    for (int h = 0; h < 2; h++) {
                        float c0 = sacc[nA + h][0], c1 = sacc[nA + h][1];
                        float c2 = sacc[nA + h][2], c3 = sacc[nA + h][3];
                        uint32_t h01 = packbf(c1, c0);
                        uint32_t h23 = packbf(c3, c2);
                        ah[m][2 * h]     = h01;
                        ah[m][2 * h + 1] = h23;
                        float r0 = c0 - __uint_as_float(h01 << 16);
                        float r1 = c1 - __uint_as_float(h01 & 0xffff0000u);
                        float r2 = c2 - __uint_as_float(h23 << 16);
                        float r3 = c3 - __uint_as_float(h23 & 0xffff0000u);
                        al[m][2 * h]     = packbf(r1, r0);
                        al[m][2 * h + 1] = packbf(r3, r2);
                    }
                }
                const uint32_t co = ((hf * 2 + jp) * 32 + lc8 * 8) * 2;
                #pragma unroll
                for (int ab2 = 0; ab2 < 5; ab2++) {
                    const int a0 = 2 * ab2, a1 = a0 + 1;
                    uint32_t vh0[4], vh1[4], vl0[4], vl1[4];
                    ldsm4(vh0, VH + (a0 * 8 + lr8) * VROWB + co);
                    ldsm4(vh1, VH + (a1 * 8 + lr8) * VROWB + co);
                    mma16816(oacc[a0], ah[0], vh0[0], vh0[1]);
                    mma16816(oacc[a1], ah[0], vh1[0], vh1[1]);
                    mma16816(oacc[a0], ah[1], vh0[2], vh0[3]);
                    mma16816(oacc[a1], ah[1], vh1[2], vh1[3]);
                    mma16816(oacc[a0], al[0], vh0[0], vh0[1]);
                    mma16816(oacc[a1], al[0], vh1[0], vh1[1]);
                    mma16816(oacc[a0], al[1], vh0[2], vh0[3]);
                    mma16816(oacc[a1], al[1], vh1[2], vh1[3]);
                    ldsm4(vl0, VL + (a0 * 8 + lr8) * VROWB + co);
                    ldsm4(vl1, VL + (a1 * 8 + lr8) * VROWB + co);
                    mma16816(oacc[a0], ah[0], vl0[0], vl0[1]);
                    mma16816(oacc[a1], ah[0], vl1[0], vl1[1]);
                    mma16816(oacc[a0], ah[1], vl0[2], vl0[3]);
                    mma16816(oacc[a1], ah[1], vl1[2], vl1[3]);
                }
            }
        }
        __syncthreads();
    }

    // ---- epilogue: write unnormalized O + l ----
    const int r  = lane >> 2, tq = lane & 3;
    const int qrow0 = q0 + 16 * warp + r;
    const int qrow1 = qrow0 + 8;
    float* Ob = g_Opart + ((size_t)sp * NK + k) * NB * GA;
    #pragma unroll
    for (int ab = 0; ab < 10; ab++) {
        const int col = ab * 8 + tq * 2;
        Ob[(size_t)qrow0 * GA + col]     = oacc[ab][0];
        Ob[(size_t)qrow0 * GA + col + 1] = oacc[ab][1];
        Ob[(size_t)qrow1 * GA + col]     = oacc[ab][2];
        Ob[(size_t)qrow1 * GA + col + 1] = oacc[ab][3];
    }
    lacc0 += __shfl_xor_sync(0xffffffffu, lacc0, 1);
    lacc0 += __shfl_xor_sync(0xffffffffu, lacc0, 2);
    lacc1 += __shfl_xor_sync(0xffffffffu, lacc1, 1);
    lacc1 += __shfl_xor_sync(0xffffffffu, lacc1, 2);
    if (tq == 0) {
        float* Lb = g_lsum + ((size_t)sp * NK + k) * NB;
        Lb[qrow0] = lacc0;
        Lb[qrow1] = lacc1;
    }
}

// ---------------------------------------------------------------------------
// Merge: sum splits (shared m-hat => plain sums), normalize, k-combine.
// ---------------------------------------------------------------------------
__global__ __launch_bounds__(256) void merge_kernel(
    const float* __restrict__ assign, float* __restrict__ out)
{
    int idx = blockIdx.x * 256 + threadIdx.x;
    if (idx >= NB * GA) return;
    int b  = idx / GA;
    int ga = idx - b * GA;
    int g  = ga >> 3;

    float aw[NK], mxw = -CUDART_INF_F;
    #pragma unroll
    for (int k = 0; k < NK; k++) {
        aw[k] = __ldg(assign + g * NK + k);
        mxw = fmaxf(mxw, aw[k]);
    }
    float wsum = 0.f;
    #pragma unroll
    for (int k = 0; k < NK; k++) { aw[k] = __expf(aw[k] - mxw); wsum += aw[k]; }
    float winv = 1.f / wsum;

    float acc = 0.f;
    #pragma unroll
    for (int k = 0; k < NK; k++) {
        float O = 0.f, L = 0.f;
        #pragma unroll
        for (int s = 0; s < NSPLIT; s++) {
            O += g_Opart[(((size_t)s * NK + k) * NB + b) * GA + ga];
            L += g_lsum[((size_t)s * NK + k) * NB + b];
        }
        acc += aw[k] * (O / L);
    }
    out[idx] = acc * winv;
}

// ---------------------------------------------------------------------------
extern "C" void kernel_launch(void* const* d_in, const int* in_sizes, int n_in,
                              void* d_out, int out_size)
{
    (void)in_sizes; (void)n_in; (void)out_size;
    const float* state  = (const float*)d_in[0];
    const float* hist   = (const float*)d_in[1];
    const float* jah    = (const float*)d_in[2];
    const float* W0 = (const float*)d_in[3];
    const float* b0 = (const float*)d_in[4];
    const float* W1 = (const float*)d_in[5];
    const float* b1 = (const float*)d_in[6];
    const float* W2 = (const float*)d_in[7];
    const float* b2 = (const float*)d_in[8];
    const float* assign = (const float*)d_in[9];
    float* out = (float*)d_out;

    wprep_kernel<<<160, 256>>>(W0, W1, W2);
    vtrans_kernel<<<NH / 128, 256>>>(jah);

    cudaFuncSetAttribute(encoder_k_kernel,
                         cudaFuncAttributeMaxDynamicSharedMemorySize, E_TOTAL);
    encoder_k_kernel<<<dim3(NH / 128, NK), 256, E_TOTAL>>>(hist, b0, b1, b2);

    encoder_kernel<<<dim3(NB / 64, NK), 256>>>(state, NB,
                                               W0, b0, W1, b1, W2, b2);

    cudaFuncSetAttribute(attn_kernel,
                         cudaFuncAttributeMaxDynamicSharedMemorySize, SM_TOTAL);
    attn_kernel<<<dim3(NB / MQ, NK, NSPLIT), ATHR, SM_TOTAL>>>();

    merge_kernel<<<(NB * GA + 255) / 256, 256>>>(assign, out);
}

// round 14
// speedup vs baseline: 1.5744x; 1.5744x over previous
#include <cuda_runtime.h>
#include <cuda_bf16.h>
#include <math_constants.h>
#include <cstdint>

#define NB   1024
#define NH   16384
#define SDIM 32
#define HID  64
#define NK   4
#define GA   80

#define MQ   256
#define KT   128
#define NSPLIT 8
#define KEYS_PER_CTA (NH / NSPLIT)   // 2048
#define TILES (KEYS_PER_CTA / KT)    // 16
#define ATHR 512

#define KROWB 144    // K/Q smem row stride bytes (64 bf16 + 16B pad)
#define VROWB 272    // V smem row stride bytes (128 bf16 + 16B pad)

// attn smem byte offsets
#define SM_MHAT 0                            // 256 floats
#define SM_QLO  1024                         // 256 * KROWB = 36864
#define SM_KH0  (SM_QLO + 256 * KROWB)       // 37888
#define SM_QHI  SM_KH0                       // Q-hi staging aliases KH0+KL0 (256 rows)
#define SM_KL0  (SM_KH0 + 128 * KROWB)       // 56320
#define SM_KH1  (SM_KL0 + 128 * KROWB)       // 74752
#define SM_KL1  (SM_KH1 + 128 * KROWB)       // 93184
#define SM_VH0  (SM_KL1 + 128 * KROWB)       // 111616
#define SM_VL0  (SM_VH0 + 80 * VROWB)        // 133376
#define SM_VH1  (SM_VL0 + 80 * VROWB)        // 155136
#define SM_VL1  (SM_VH1 + 80 * VROWB)        // 176896
#define SM_TOTAL (SM_VL1 + 80 * VROWB)       // 198656

// encoder smem byte offsets
#define EROWB 144
#define E_XH  0
#define E_XL  18432
#define E_WH  36864
#define E_WL  46080
#define E_TOTAL 55296

// global scratch
__device__ float         g_enc_s[NK * NB * HID];
__device__ __nv_bfloat16 g_Khi[NK * NH * HID];
__device__ __nv_bfloat16 g_Klo[NK * NH * HID];
__device__ __nv_bfloat16 g_VThi[GA * NH];
__device__ __nv_bfloat16 g_VTlo[GA * NH];
__device__ float         g_Kmax[NK];
__device__ float         g_Opart[NSPLIT * NK * NB * GA];
__device__ float         g_lsum[NSPLIT * NK * NB];
// transposed + bf16-split weights [k][out][in]
__device__ __nv_bfloat16 g_W0Thi[NK * HID * SDIM];
__device__ __nv_bfloat16 g_W0Tlo[NK * HID * SDIM];
__device__ __nv_bfloat16 g_W1Thi[NK * HID * HID];
__device__ __nv_bfloat16 g_W1Tlo[NK * HID * HID];
__device__ __nv_bfloat16 g_W2Thi[NK * HID * HID];
__device__ __nv_bfloat16 g_W2Tlo[NK * HID * HID];

// ---------------- helpers ----------------
__device__ __forceinline__ void cp16(uint32_t sdst, const void* gsrc) {
    asm volatile("cp.async.cg.shared.global [%0], [%1], 16;" :: "r"(sdst), "l"(gsrc));
}
#define CP_COMMIT() asm volatile("cp.async.commit_group;" ::: "memory")
#define CP_WAIT(n)  asm volatile("cp.async.wait_group %0;" :: "n"(n) : "memory")

__device__ __forceinline__ void ldsm4(uint32_t* r, uint32_t addr) {
    asm volatile("ldmatrix.sync.aligned.m8n8.x4.shared.b16 {%0,%1,%2,%3}, [%4];"
        : "=r"(r[0]), "=r"(r[1]), "=r"(r[2]), "=r"(r[3]) : "r"(addr));
}
__device__ __forceinline__ void mma16816(float* d, const uint32_t* a,
                                         uint32_t b0, uint32_t b1) {
    asm volatile("mma.sync.aligned.m16n8k16.row.col.f32.bf16.bf16.f32 "
        "{%0,%1,%2,%3}, {%4,%5,%6,%7}, {%8,%9}, {%0,%1,%2,%3};"
        : "+f"(d[0]), "+f"(d[1]), "+f"(d[2]), "+f"(d[3])
        : "r"(a[0]), "r"(a[1]), "r"(a[2]), "r"(a[3]), "r"(b0), "r"(b1));
}
__device__ __forceinline__ uint32_t packbf(float hi, float lo) {
    uint32_t r;
    asm("cvt.rn.bf16x2.f32 %0, %1, %2;" : "=r"(r) : "f"(hi), "f"(lo));
    return r;
}

// ---------------------------------------------------------------------------
// Weight prep: transpose to [k][out][in] and bf16 hi/lo split.
// ---------------------------------------------------------------------------
__global__ __launch_bounds__(256) void wprep_kernel(
    const float* __restrict__ W0, const float* __restrict__ W1,
    const float* __restrict__ W2)
{
    int idx = blockIdx.x * 256 + threadIdx.x;
    float f;
    __nv_bfloat16* dh;
    __nv_bfloat16* dl;
    int d;
    if (idx < NK * HID * SDIM) {
        int k = idx / (HID * SDIM), r = idx % (HID * SDIM);
        int o = r / SDIM, i = r % SDIM;
        f = W0[((size_t)k * SDIM + i) * HID + o];
        dh = g_W0Thi; dl = g_W0Tlo; d = idx;
    } else if (idx < NK * HID * SDIM + NK * HID * HID) {
        int x = idx - NK * HID * SDIM;
        int k = x / (HID * HID), r = x % (HID * HID);
        int o = r / HID, i = r % HID;
        f = W1[((size_t)k * HID + i) * HID + o];
        dh = g_W1Thi; dl = g_W1Tlo; d = x;
    } else if (idx < NK * HID * SDIM + 2 * NK * HID * HID) {
        int x = idx - NK * HID * SDIM - NK * HID * HID;
        int k = x / (HID * HID), r = x % (HID * HID);
        int o = r / HID, i = r % HID;
        f = W2[((size_t)k * HID + i) * HID + o];
        dh = g_W2Thi; dl = g_W2Tlo; d = x;
    } else return;
    __nv_bfloat16 h = __float2bfloat16(f);
    dh[d] = h;
    dl[d] = __float2bfloat16(f - __bfloat162float(h));
}

// ---------------------------------------------------------------------------
// Unified encoder on tensor cores: 3x (Linear+ReLU), 3-pass bf16 error-split.
// Grid (rows/128, NK), 256 threads (8 warps x 16 rows).
// mode 1: emit g_Khi/g_Klo + per-k max row norm.  mode 0: emit fp32 g_enc_s.
// ---------------------------------------------------------------------------
__global__ __launch_bounds__(256) void encoder_k_kernel(
    const float* __restrict__ x, int mode,
    const float* __restrict__ b0, const float* __restrict__ b1,
    const float* __restrict__ b2)
{
    extern __shared__ char esm[];
    const uint32_t sb = (uint32_t)__cvta_generic_to_shared(esm);
    const int tid  = threadIdx.x;
    const int warp = tid >> 5;
    const int lane = tid & 31;
    const int k    = blockIdx.y;
    const int row0 = blockIdx.x * 128;

    // X0: 128 rows x 32 cols fp32 -> bf16 hi/lo smem
    #pragma unroll
    for (int it = 0; it < 16; it++) {
        int idx = tid + it * 256;
        int row = idx >> 5, c = idx & 31;
        float f = x[(size_t)(row0 + row) * SDIM + c];
        __nv_bfloat16 h = __float2bfloat16(f);
        *(__nv_bfloat16*)(esm + E_XH + row * EROWB + c * 2) = h;
        *(__nv_bfloat16*)(esm + E_XL + row * EROWB + c * 2) =
            __float2bfloat16(f - __bfloat162float(h));
    }
    // W0T: 64 rows x 32 bf16 (64B) via cp.async
    {
        int row = tid >> 2, c = tid & 3;
        cp16(sb + E_WH + row * EROWB + c * 16,
             g_W0Thi + ((size_t)k * HID + row) * SDIM + c * 8);
        cp16(sb + E_WL + row * EROWB + c * 16,
             g_W0Tlo + ((size_t)k * HID + row) * SDIM + c * 8);
    }
    CP_COMMIT();
    CP_WAIT(0);
    __syncthreads();

    const uint32_t aro  = (16 * warp + (lane & 15)) * EROWB;
    const uint32_t asel = ((lane >> 4) & 1) * 8;
    const uint32_t lr8  = lane & 7, lc8 = (lane >> 3) & 3;
    const int r = lane >> 2, tq = lane & 3;
    const int wrow = 16 * warp + r;

    float acc[8][4];

    // ---- layer 0 (K=32) ----
    #pragma unroll
    for (int n = 0; n < 8; n++)
        #pragma unroll
        for (int e = 0; e < 4; e++) acc[n][e] = 0.f;
    {
        uint32_t ah[2][4], al[2][4];
        #pragma unroll
        for (int kf = 0; kf < 2; kf++) {
            ldsm4(ah[kf], sb + E_XH + aro + (kf * 16 + asel) * 2);
            ldsm4(al[kf], sb + E_XL + aro + (kf * 16 + asel) * 2);
        }
        const uint32_t co = (lc8 * 8) * 2;
        #pragma unroll
        for (int n = 0; n < 8; n++) {
            uint32_t bh[4], bl[4];
            ldsm4(bh, sb + E_WH + (n * 8 + lr8) * EROWB + co);
            ldsm4(bl, sb + E_WL + (n * 8 + lr8) * EROWB + co);
            mma16816(acc[n], ah[0], bh[0], bh[1]);
            mma16816(acc[n], ah[1], bh[2], bh[3]);
            mma16816(acc[n], al[0], bh[0], bh[1]);
            mma16816(acc[n], al[1], bh[2], bh[3]);
            mma16816(acc[n], ah[0], bl[0], bl[1]);
            mma16816(acc[n], ah[1], bl[2], bl[3]);
        }
    }
    __syncthreads();   // all layer-0 reads complete

    // bias+ReLU+split -> X smem; load W1
    {
        const float* bp = b0 + k * HID;
        #pragma unroll
        for (int n = 0; n < 8; n++) {
            int col = n * 8 + tq * 2;
            float ba = __ldg(bp + col), bb = __ldg(bp + col + 1);
            float h0 = fmaxf(acc[n][0] + ba, 0.f);
            float h1 = fmaxf(acc[n][1] + bb, 0.f);
            float h2 = fmaxf(acc[n][2] + ba, 0.f);
            float h3 = fmaxf(acc[n][3] + bb, 0.f);
            uint32_t w01 = packbf(h1, h0), w23 = packbf(h3, h2);
            float r0 = h0 - __uint_as_float(w01 << 16);
            float r1 = h1 - __uint_as_float(w01 & 0xffff0000u);
            float r2 = h2 - __uint_as_float(w23 << 16);
            float r3 = h3 - __uint_as_float(w23 & 0xffff0000u);
            *(uint32_t*)(esm + E_XH + wrow * EROWB + col * 2)       = w01;
            *(uint32_t*)(esm + E_XH + (wrow + 8) * EROWB + col * 2) = w23;
            *(uint32_t*)(esm + E_XL + wrow * EROWB + col * 2)       = packbf(r1, r0);
            *(uint32_t*)(esm + E_XL + (wrow + 8) * EROWB + col * 2) = packbf(r3, r2);
        }
        #pragma unroll
        for (int it = 0; it < 2; it++) {
            int idx = tid + it * 256;
            int row = idx >> 3, c = idx & 7;
            cp16(sb + E_WH + row * EROWB + c * 16,
                 g_W1Thi + ((size_t)k * HID + row) * HID + c * 8);
            cp16(sb + E_WL + row * EROWB + c * 16,
                 g_W1Tlo + ((size_t)k * HID + row) * HID + c * 8);
        }
        CP_COMMIT();
        CP_WAIT(0);
        __syncthreads();
    }

    // ---- layers 1 & 2 (K=64) ----
    #pragma unroll
    for (int layer = 1; layer <= 2; layer++) {
        #pragma unroll
        for (int n = 0; n < 8; n++)
            #pragma unroll
            for (int e = 0; e < 4; e++) acc[n][e] = 0.f;
        uint32_t ah[4][4], al[4][4];
        #pragma unroll
        for (int kf = 0; kf < 4; kf++) {
            ldsm4(ah[kf], sb + E_XH + aro + (kf * 16 + asel) * 2);
            ldsm4(al[kf], sb + E_XL + aro + (kf * 16 + asel) * 2);
        }
        #pragma unroll
        for (int dp = 0; dp < 2; dp++) {
            const uint32_t co = (dp * 32 + lc8 * 8) * 2;
            const int k0 = 2 * dp, k1 = 2 * dp + 1;
            #pragma unroll
            for (int n = 0; n < 8; n++) {
                uint32_t bh[4], bl[4];
                ldsm4(bh, sb + E_WH + (n * 8 + lr8) * EROWB + co);
                ldsm4(bl, sb + E_WL + (n * 8 + lr8) * EROWB + co);
                mma16816(acc[n], ah[k0], bh[0], bh[1]);
                mma16816(acc[n], ah[k1], bh[2], bh[3]);
                mma16816(acc[n], al[k0], bh[0], bh[1]);
                mma16816(acc[n], al[k1], bh[2], bh[3]);
                mma16816(acc[n], ah[k0], bl[0], bl[1]);
                mma16816(acc[n], ah[k1], bl[2], bl[3]);
            }
        }
        __syncthreads();

        if (layer == 1) {
            const float* bp = b1 + k * HID;
            #pragma unroll
            for (int n = 0; n < 8; n++) {
                int col = n * 8 + tq * 2;
                float ba = __ldg(bp + col), bb = __ldg(bp + col + 1);
                float h0 = fmaxf(acc[n][0] + ba, 0.f);
                float h1 = fmaxf(acc[n][1] + bb, 0.f);
                float h2 = fmaxf(acc[n][2] + ba, 0.f);
                float h3 = fmaxf(acc[n][3] + bb, 0.f);
                uint32_t w01 = packbf(h1, h0), w23 = packbf(h3, h2);
                float r0 = h0 - __uint_as_float(w01 << 16);
                float r1 = h1 - __uint_as_float(w01 & 0xffff0000u);
                float r2 = h2 - __uint_as_float(w23 << 16);
                float r3 = h3 - __uint_as_float(w23 & 0xffff0000u);
                *(uint32_t*)(esm + E_XH + wrow * EROWB + col * 2)       = w01;
                *(uint32_t*)(esm + E_XH + (wrow + 8) * EROWB + col * 2) = w23;
                *(uint32_t*)(esm + E_XL + wrow * EROWB + col * 2)       = packbf(r1, r0);
                *(uint32_t*)(esm + E_XL + (wrow + 8) * EROWB + col * 2) = packbf(r3, r2);
            }
            #pragma unroll
            for (int it = 0; it < 2; it++) {
                int idx = tid + it * 256;
                int row = idx >> 3, c = idx & 7;
                cp16(sb + E_WH + row * EROWB + c * 16,
                     g_W2Thi + ((size_t)k * HID + row) * HID + c * 8);
                cp16(sb + E_WL + row * EROWB + c * 16,
                     g_W2Tlo + ((size_t)k * HID + row) * HID + c * 8);
            }
            CP_COMMIT();
            CP_WAIT(0);
            __syncthreads();
        } else if (mode == 1) {
            // final: write g_Khi/g_Klo + row norms
            const float* bp = b2 + k * HID;
            const size_t ga = (size_t)k * NH + row0 + wrow;
            float sA = 0.f, sB = 0.f;
            #pragma unroll
            for (int n = 0; n < 8; n++) {
                int col = n * 8 + tq * 2;
                float ba = __ldg(bp + col), bb = __ldg(bp + col + 1);
                float h0 = fmaxf(acc[n][0] + ba, 0.f);
                float h1 = fmaxf(acc[n][1] + bb, 0.f);
                float h2 = fmaxf(acc[n][2] + ba, 0.f);
                float h3 = fmaxf(acc[n][3] + bb, 0.f);
                sA += h0 * h0 + h1 * h1;
                sB += h2 * h2 + h3 * h3;
                uint32_t w01 = packbf(h1, h0), w23 = packbf(h3, h2);
                float r0 = h0 - __uint_as_float(w01 << 16);
                float r1 = h1 - __uint_as_float(w01 & 0xffff0000u);
                float r2 = h2 - __uint_as_float(w23 << 16);
                float r3 = h3 - __uint_as_float(w23 & 0xffff0000u);
                *(uint32_t*)((__nv_bfloat16*)g_Khi + ga * HID + col)       = w01;
                *(uint32_t*)((__nv_bfloat16*)g_Khi + (ga + 8) * HID + col) = w23;
                *(uint32_t*)((__nv_bfloat16*)g_Klo + ga * HID + col)       = packbf(r1, r0);
                *(uint32_t*)((__nv_bfloat16*)g_Klo + (ga + 8) * HID + col) = packbf(r3, r2);
            }
            sA += __shfl_xor_sync(0xffffffffu, sA, 1);
            sA += __shfl_xor_sync(0xffffffffu, sA, 2);
            sB += __shfl_xor_sync(0xffffffffu, sB, 1);
            sB += __shfl_xor_sync(0xffffffffu, sB, 2);
            if (tq == 0) {
                float mx = fmaxf(sqrtf(sA), sqrtf(sB));
                atomicMax((int*)&g_Kmax[k], __float_as_int(mx));
            }
        } else {
            // final: write fp32 g_enc_s (state encoder)
            const float* bp = b2 + k * HID;
            const size_t base = ((size_t)k * NB + row0 + wrow) * HID;
            #pragma unroll
            for (int n = 0; n < 8; n++) {
                int col = n * 8 + tq * 2;
                float ba = __ldg(bp + col), bb = __ldg(bp + col + 1);
                g_enc_s[base + col]               = fmaxf(acc[n][0] + ba, 0.f);
                g_enc_s[base + col + 1]           = fmaxf(acc[n][1] + bb, 0.f);
                g_enc_s[base + 8 * HID + col]     = fmaxf(acc[n][2] + ba, 0.f);
                g_enc_s[base + 8 * HID + col + 1] = fmaxf(acc[n][3] + bb, 0.f);
            }
        }
    }
}

// ---------------------------------------------------------------------------
// V transpose + bf16 split: g_VThi/lo[a][j] = split(V[j][a])
// ---------------------------------------------------------------------------
__global__ __launch_bounds__(256) void vtrans_kernel(const float* __restrict__ V)
{
    __shared__ float sm[128 * GA];
    const int j0 = blockIdx.x * 128;
    for (int i = threadIdx.x; i < 128 * GA; i += 256)
        sm[i] = V[(size_t)j0 * GA + i];
    __syncthreads();
    for (int i = threadIdx.x; i < 128 * GA; i += 256) {
        int a = i >> 7, j = i & 127;
        float f = sm[j * GA + a];
        __nv_bfloat16 h = __float2bfloat16(f);
        __nv_bfloat16 lo = __float2bfloat16(f - __bfloat162float(h));
        g_VThi[(size_t)a * NH + j0 + j] = h;
        g_VTlo[(size_t)a * NH + j0 + j] = lo;
    }
}

// ---------------------------------------------------------------------------
// mma.sync flash attention (unchanged from R10). Grid (4, NK, NSPLIT), 512 thr.
// ---------------------------------------------------------------------------
__device__ __forceinline__ void load_tile(uint32_t sb, int k, int key0, int buf,
                                          int tid)
{
    const uint32_t kh = sb + (buf ? SM_KH1 : SM_KH0);
    const uint32_t kl = sb + (buf ? SM_KL1 : SM_KL0);
    const char* shi = (const char*)(g_Khi + ((size_t)k * NH + key0) * HID);
    const char* slo = (const char*)(g_Klo + ((size_t)k * NH + key0) * HID);
    #pragma unroll
    for (int it = 0; it < 2; it++) {
        int idx = tid + it * ATHR;              // 0..1023
        int row = idx >> 3, c = idx & 7;
        uint32_t doff = row * KROWB + c * 16;
        size_t goff = (size_t)row * 128 + c * 16;
        cp16(kh + doff, shi + goff);
        cp16(kl + doff, slo + goff);
    }
    const uint32_t vh = sb + (buf ? SM_VH1 : SM_VH0);
    const uint32_t vl = sb + (buf ? SM_VL1 : SM_VL0);
    const char* vhi = (const char*)g_VThi + (size_t)key0 * 2;
    const char* vlo = (const char*)g_VTlo + (size_t)key0 * 2;
    #pragma unroll
    for (int it = 0; it < 3; it++) {
        int idx = tid + it * ATHR;              // 0..1535, need 1280
        if (idx < 1280) {
            int a = idx >> 4, c = idx & 15;
            uint32_t doff = a * VROWB + c * 16;
            size_t goff = (size_t)a * NH * 2 + c * 16;
            cp16(vh + doff, vhi + goff);
            cp16(vl + doff, vlo + goff);
        }
    }
}

__global__ __launch_bounds__(ATHR, 1) void attn_kernel()
{
    extern __shared__ char smem[];
    const uint32_t sb = (uint32_t)__cvta_generic_to_shared(smem);
    const int tid  = threadIdx.x;
    const int warp = tid >> 5;
    const int lane = tid & 31;
    const int k    = blockIdx.y;
    const int sp   = blockIdx.z;
    const int q0   = blockIdx.x * MQ;
    const int kb0  = sp * KEYS_PER_CTA;

    const float* Qg = g_enc_s + ((size_t)k * NB + q0) * HID;
    float* MH = (float*)(smem + SM_MHAT);

    // m-hat per query row (fixed softmax bound)
    if (tid < MQ) {
        const float4* qr = (const float4*)(Qg + tid * HID);
        float ss = 0.f;
        #pragma unroll
        for (int i = 0; i < 16; i++) {
            float4 f = qr[i];
            ss += f.x * f.x + f.y * f.y + f.z * f.z + f.w * f.w;
        }
        MH[tid] = sqrtf(ss) * g_Kmax[k];
    }

    // stage Q: hi into SM_QHI (aliases K buf0, 256 rows), lo into SM_QLO
    {
        int row = tid >> 1, half = tid & 1;
        const float* qr = Qg + row * HID + half * 32;
        char* dh = smem + SM_QHI + row * KROWB + half * 64;
        char* dl = smem + SM_QLO + row * KROWB + half * 64;
        #pragma unroll
        for (int i = 0; i < 8; i++) {
            float4 f = *(const float4*)(qr + i * 4);
            uint32_t h0 = packbf(f.y, f.x);
            uint32_t h1 = packbf(f.w, f.z);
            float r0 = f.x - __uint_as_float(h0 << 16);
            float r1 = f.y - __uint_as_float(h0 & 0xffff0000u);
            float r2 = f.z - __uint_as_float(h1 << 16);
            float r3 = f.w - __uint_as_float(h1 & 0xffff0000u);
            *(uint32_t*)(dh + i * 8)     = h0;
            *(uint32_t*)(dh + i * 8 + 4) = h1;
            *(uint32_t*)(dl + i * 8)     = packbf(r1, r0);
            *(uint32_t*)(dl + i * 8 + 4) = packbf(r3, r2);
        }
    }
    __syncthreads();

    // Q-hi fragments to registers (Q-lo stays resident in SM_QLO)
    uint32_t qh[4][4];
    const uint32_t qro = (16 * warp + (lane & 15)) * KROWB;
    const uint32_t qsel = ((lane >> 4) & 1) * 8;
    #pragma unroll
    for (int kk = 0; kk < 4; kk++)
        ldsm4(qh[kk], sb + SM_QHI + qro + (kk * 16 + qsel) * 2);
    const float mh0 = MH[16 * warp + (lane >> 2)];
    const float mh1 = MH[16 * warp + (lane >> 2) + 8];
    __syncthreads();   // Q-hi staging area now free for K tiles

    load_tile(sb, k, kb0, 0, tid);
    CP_COMMIT();

    float oacc[10][4];
    #pragma unroll
    for (int ab = 0; ab < 10; ab++)
        #pragma unroll
        for (int e = 0; e < 4; e++) oacc[ab][e] = 0.f;
    float lacc0 = 0.f, lacc1 = 0.f;

    const uint32_t lr8 = (lane & 7), lc8 = ((lane >> 3) & 3);

    for (int t = 0; t < TILES; t++) {
        if (t + 1 < TILES) {
            load_tile(sb, k, kb0 + (t + 1) * KT, (t + 1) & 1, tid);
            CP_COMMIT();
            CP_WAIT(1);
        } else {
            CP_WAIT(0);
        }
        __syncthreads();

        const uint32_t KH = sb + ((t & 1) ? SM_KH1 : SM_KH0);
        const uint32_t KL = sb + ((t & 1) ? SM_KL1 : SM_KL0);
        const uint32_t VH = sb + ((t & 1) ? SM_VH1 : SM_VH0);
        const uint32_t VL = sb + ((t & 1) ? SM_VL1 : SM_VL0);

        #pragma unroll
        for (int hf = 0; hf < 2; hf++) {
            // ---- scores for 64-key half: S = QhiKhi + QloKhi + QhiKlo ----
            float sacc[8][4];
            #pragma unroll
            for (int nb = 0; nb < 8; nb++)
                #pragma unroll
                for (int e = 0; e < 4; e++) sacc[nb][e] = 0.f;

            #pragma unroll
            for (int dp = 0; dp < 2; dp++) {
                uint32_t qlA[4], qlB[4];
                ldsm4(qlA, sb + SM_QLO + qro + ((2 * dp) * 16 + qsel) * 2);
                ldsm4(qlB, sb + SM_QLO + qro + ((2 * dp + 1) * 16 + qsel) * 2);
                const uint32_t co = (dp * 32 + lc8 * 8) * 2;
                const int k0 = 2 * dp, k1 = 2 * dp + 1;
                #pragma unroll
                for (int nb2 = 0; nb2 < 4; nb2++) {
                    const int n0 = hf * 8 + 2 * nb2, n1 = n0 + 1;
                    const int l0 = 2 * nb2, l1 = l0 + 1;
                    uint32_t bh0[4], bl0[4], bh1[4], bl1[4];
                    ldsm4(bh0, KH + (n0 * 8 + lr8) * KROWB + co);
                    ldsm4(bh1, KH + (n1 * 8 + lr8) * KROWB + co);
                    ldsm4(bl0, KL + (n0 * 8 + lr8) * KROWB + co);
                    ldsm4(bl1, KL + (n1 * 8 + lr8) * KROWB + co);
                    mma16816(sacc[l0], qh[k0], bh0[0], bh0[1]);
                    mma16816(sacc[l1], qh[k0], bh1[0], bh1[1]);
                    mma16816(sacc[l0], qh[k1], bh0[2], bh0[3]);
                    mma16816(sacc[l1], qh[k1], bh1[2], bh1[3]);
                    mma16816(sacc[l0], qlA, bh0[0], bh0[1]);
                    mma16816(sacc[l1], qlA, bh1[0], bh1[1]);
                    mma16816(sacc[l0], qlB, bh0[2], bh0[3]);
                    mma16816(sacc[l1], qlB, bh1[2], bh1[3]);
                    mma16816(sacc[l0], qh[k0], bl0[0], bl0[1]);
                    mma16816(sacc[l1], qh[k0], bl1[0], bl1[1]);
                    mma16816(sacc[l0], qh[k1], bl0[2], bl0[3]);
                    mma16816(sacc[l1], qh[k1], bl1[2], bl1[3]);
                }
            }

            // ---- softmax with fixed bound ----
            #pragma unroll
            for (int nb = 0; nb < 8; nb++) {
                float p0 = __expf(sacc[nb][0] - mh0);
                float p1 = __expf(sacc[nb][1] - mh0);
                float p2 = __expf(sacc[nb][2] - mh1);
                float p3 = __expf(sacc[nb][3] - mh1);
                lacc0 += p0 + p1;
                lacc1 += p2 + p3;
                sacc[nb][0] = p0; sacc[nb][1] = p1;
                sacc[nb][2] = p2; sacc[nb][3] = p3;
            }

            // ---- PV over this key half: O += PhiVhi + PloVhi + PhiVlo ----
            #pragma unroll
            for (int jp = 0; jp < 2; jp++) {
                uint32_t ah[2][4], al[2][4];
                #pragma unroll
                for (int m = 0; m < 2; m++) {
                    const int nA = 4 * jp + 2 * m;
                    #pragma unroll
                    for (int h = 0; h < 2; h++) {
                        float c0 = sacc[nA + h][0], c1 = sacc[nA + h][1];
                        float c2 = sacc[nA + h][2], c3 = sacc[nA + h][3];
                        uint32_t h01 = packbf(c1, c0);
                        uint32_t h23 = packbf(c3, c2);
                        ah[m][2 * h]     = h01;
                        ah[m][2 * h + 1] = h23;
                        float r0 = c0 - __uint_as_float(h01 << 16);
                        float r1 = c1 - __uint_as_float(h01 & 0xffff0000u);
                        float r2 = c2 - __uint_as_float(h23 << 16);
                        float r3 = c3 - __uint_as_float(h23 & 0xffff0000u);
                        al[m][2 * h]     = packbf(r1, r0);
                        al[m][2 * h + 1] = packbf(r3, r2);
                    }
                }
                const uint32_t co = ((hf * 2 + jp) * 32 + lc8 * 8) * 2;
                #pragma unroll
                for (int ab2 = 0; ab2 < 5; ab2++) {
                    const int a0 = 2 * ab2, a1 = a0 + 1;
                    uint32_t vh0[4], vh1[4], vl0[4], vl1[4];
                    ldsm4(vh0, VH + (a0 * 8 + lr8) * VROWB + co);
                    ldsm4(vh1, VH + (a1 * 8 + lr8) * VROWB + co);
                    mma16816(oacc[a0], ah[0], vh0[0], vh0[1]);
                    mma16816(oacc[a1], ah[0], vh1[0], vh1[1]);
                    mma16816(oacc[a0], ah[1], vh0[2], vh0[3]);
                    mma16816(oacc[a1], ah[1], vh1[2], vh1[3]);
                    mma16816(oacc[a0], al[0], vh0[0], vh0[1]);
                    mma16816(oacc[a1], al[0], vh1[0], vh1[1]);
                    mma16816(oacc[a0], al[1], vh0[2], vh0[3]);
                    mma16816(oacc[a1], al[1], vh1[2], vh1[3]);
                    ldsm4(vl0, VL + (a0 * 8 + lr8) * VROWB + co);
                    ldsm4(vl1, VL + (a1 * 8 + lr8) * VROWB + co);
                    mma16816(oacc[a0], ah[0], vl0[0], vl0[1]);
                    mma16816(oacc[a1], ah[0], vl1[0], vl1[1]);
                    mma16816(oacc[a0], ah[1], vl0[2], vl0[3]);
                    mma16816(oacc[a1], ah[1], vl1[2], vl1[3]);
                }
            }
        }
        __syncthreads();
    }

    // ---- epilogue: write unnormalized O + l ----
    const int r  = lane >> 2, tq = lane & 3;
    const int qrow0 = q0 + 16 * warp + r;
    const int qrow1 = qrow0 + 8;
    float* Ob = g_Opart + ((size_t)sp * NK + k) * NB * GA;
    #pragma unroll
    for (int ab = 0; ab < 10; ab++) {
        const int col = ab * 8 + tq * 2;
        Ob[(size_t)qrow0 * GA + col]     = oacc[ab][0];
        Ob[(size_t)qrow0 * GA + col + 1] = oacc[ab][1];
        Ob[(size_t)qrow1 * GA + col]     = oacc[ab][2];
        Ob[(size_t)qrow1 * GA + col + 1] = oacc[ab][3];
    }
    lacc0 += __shfl_xor_sync(0xffffffffu, lacc0, 1);
    lacc0 += __shfl_xor_sync(0xffffffffu, lacc0, 2);
    lacc1 += __shfl_xor_sync(0xffffffffu, lacc1, 1);
    lacc1 += __shfl_xor_sync(0xffffffffu, lacc1, 2);
    if (tq == 0) {
        float* Lb = g_lsum + ((size_t)sp * NK + k) * NB;
        Lb[qrow0] = lacc0;
        Lb[qrow1] = lacc1;
    }
}

// ---------------------------------------------------------------------------
// Merge: sum splits (shared m-hat => plain sums), normalize, k-combine.
// ---------------------------------------------------------------------------
__global__ __launch_bounds__(256) void merge_kernel(
    const float* __restrict__ assign, float* __restrict__ out)
{
    int idx = blockIdx.x * 256 + threadIdx.x;
    if (idx >= NB * GA) return;
    int b  = idx / GA;
    int ga = idx - b * GA;
    int g  = ga >> 3;

    float aw[NK], mxw = -CUDART_INF_F;
    #pragma unroll
    for (int k = 0; k < NK; k++) {
        aw[k] = __ldg(assign + g * NK + k);
        mxw = fmaxf(mxw, aw[k]);
    }
    float wsum = 0.f;
    #pragma unroll
    for (int k = 0; k < NK; k++) { aw[k] = __expf(aw[k] - mxw); wsum += aw[k]; }
    float winv = 1.f / wsum;

    float acc = 0.f;
    #pragma unroll
    for (int k = 0; k < NK; k++) {
        float O = 0.f, L = 0.f;
        #pragma unroll
        for (int s = 0; s < NSPLIT; s++) {
            O += g_Opart[(((size_t)s * NK + k) * NB + b) * GA + ga];
            L += g_lsum[((size_t)s * NK + k) * NB + b];
        }
        acc += aw[k] * (O / L);
    }
    out[idx] = acc * winv;
}

// ---------------------------------------------------------------------------
extern "C" void kernel_launch(void* const* d_in, const int* in_sizes, int n_in,
                              void* d_out, int out_size)
{
    (void)in_sizes; (void)n_in; (void)out_size;
    const float* state  = (const float*)d_in[0];
    const float* hist   = (const float*)d_in[1];
    const float* jah    = (const float*)d_in[2];
    const float* W0 = (const float*)d_in[3];
    const float* b0 = (const float*)d_in[4];
    const float* W1 = (const float*)d_in[5];
    const float* b1 = (const float*)d_in[6];
    const float* W2 = (const float*)d_in[7];
    const float* b2 = (const float*)d_in[8];
    const float* assign = (const float*)d_in[9];
    float* out = (float*)d_out;

    wprep_kernel<<<160, 256>>>(W0, W1, W2);
    vtrans_kernel<<<NH / 128, 256>>>(jah);

    cudaFuncSetAttribute(encoder_k_kernel,
                         cudaFuncAttributeMaxDynamicSharedMemorySize, E_TOTAL);
    encoder_k_kernel<<<dim3(NH / 128, NK), 256, E_TOTAL>>>(hist, 1, b0, b1, b2);
    encoder_k_kernel<<<dim3(NB / 128, NK), 256, E_TOTAL>>>(state, 0, b0, b1, b2);

    cudaFuncSetAttribute(attn_kernel,
                         cudaFuncAttributeMaxDynamicSharedMemorySize, SM_TOTAL);
    attn_kernel<<<dim3(NB / MQ, NK, NSPLIT), ATHR, SM_TOTAL>>>();

    merge_kernel<<<(NB * GA + 255) / 256, 256>>>(assign, out);
}

// round 15
// speedup vs baseline: 1.6094x; 1.0222x over previous
#include <cuda_runtime.h>
#include <cuda_bf16.h>
#include <math_constants.h>
#include <cstdint>

#define NB   1024
#define NH   16384
#define SDIM 32
#define HID  64
#define NK   4
#define GA   80

#define MQ   256
#define KT   128
#define NSPLIT 8
#define KEYS_PER_CTA (NH / NSPLIT)   // 2048
#define TILES (KEYS_PER_CTA / KT)    // 16
#define ATHR 512

#define KROWB 144    // K/Q smem row stride bytes (64 bf16 + 16B pad)
#define VROWB 272    // V smem row stride bytes (128 bf16 + 16B pad)

// attn smem byte offsets
#define SM_MHAT 0                            // 256 floats
#define SM_QLO  1024                         // 256 * KROWB = 36864
#define SM_KH0  (SM_QLO + 256 * KROWB)       // 37888
#define SM_QHI  SM_KH0                       // Q-hi staging aliases KH0+KL0 (256 rows)
#define SM_KL0  (SM_KH0 + 128 * KROWB)       // 56320
#define SM_KH1  (SM_KL0 + 128 * KROWB)       // 74752
#define SM_KL1  (SM_KH1 + 128 * KROWB)       // 93184
#define SM_VH0  (SM_KL1 + 128 * KROWB)       // 111616
#define SM_VL0  (SM_VH0 + 80 * VROWB)        // 133376
#define SM_VH1  (SM_VL0 + 80 * VROWB)        // 155136
#define SM_VL1  (SM_VH1 + 80 * VROWB)        // 176896
#define SM_TOTAL (SM_VL1 + 80 * VROWB)       // 198656

// encoder smem byte offsets
#define EROWB 144
#define E_XH  0
#define E_XL  18432
#define E_WH  36864
#define E_WL  46080
#define E_TOTAL 55296

// global scratch
__device__ float         g_enc_s[NK * NB * HID];
__device__ __nv_bfloat16 g_Khi[NK * NH * HID];
__device__ __nv_bfloat16 g_Klo[NK * NH * HID];
__device__ __nv_bfloat16 g_VThi[GA * NH];
__device__ __nv_bfloat16 g_VTlo[GA * NH];
__device__ float         g_Kmax[NK];
__device__ float         g_Opart[NSPLIT * NK * NB * GA];
__device__ float         g_lsum[NSPLIT * NK * NB];
// transposed + bf16-split weights [k][out][in]
__device__ __nv_bfloat16 g_W0Thi[NK * HID * SDIM];
__device__ __nv_bfloat16 g_W0Tlo[NK * HID * SDIM];
__device__ __nv_bfloat16 g_W1Thi[NK * HID * HID];
__device__ __nv_bfloat16 g_W1Tlo[NK * HID * HID];
__device__ __nv_bfloat16 g_W2Thi[NK * HID * HID];
__device__ __nv_bfloat16 g_W2Tlo[NK * HID * HID];

// ---------------- helpers ----------------
__device__ __forceinline__ void cp16(uint32_t sdst, const void* gsrc) {
    asm volatile("cp.async.cg.shared.global [%0], [%1], 16;" :: "r"(sdst), "l"(gsrc));
}
#define CP_COMMIT() asm volatile("cp.async.commit_group;" ::: "memory")
#define CP_WAIT(n)  asm volatile("cp.async.wait_group %0;" :: "n"(n) : "memory")

__device__ __forceinline__ void ldsm4(uint32_t* r, uint32_t addr) {
    asm volatile("ldmatrix.sync.aligned.m8n8.x4.shared.b16 {%0,%1,%2,%3}, [%4];"
        : "=r"(r[0]), "=r"(r[1]), "=r"(r[2]), "=r"(r[3]) : "r"(addr));
}
__device__ __forceinline__ void mma16816(float* d, const uint32_t* a,
                                         uint32_t b0, uint32_t b1) {
    asm volatile("mma.sync.aligned.m16n8k16.row.col.f32.bf16.bf16.f32 "
        "{%0,%1,%2,%3}, {%4,%5,%6,%7}, {%8,%9}, {%0,%1,%2,%3};"
        : "+f"(d[0]), "+f"(d[1]), "+f"(d[2]), "+f"(d[3])
        : "r"(a[0]), "r"(a[1]), "r"(a[2]), "r"(a[3]), "r"(b0), "r"(b1));
}
__device__ __forceinline__ uint32_t packbf(float hi, float lo) {
    uint32_t r;
    asm("cvt.rn.bf16x2.f32 %0, %1, %2;" : "=r"(r) : "f"(hi), "f"(lo));
    return r;
}

// ---------------------------------------------------------------------------
// Prep: blocks [0,128) transpose+split V; blocks [128,288) weight prep.
// ---------------------------------------------------------------------------
__global__ __launch_bounds__(256) void prep_kernel(
    const float* __restrict__ V,
    const float* __restrict__ W0, const float* __restrict__ W1,
    const float* __restrict__ W2)
{
    __shared__ float sm[128 * GA];
    if (blockIdx.x < 128) {
        const int j0 = blockIdx.x * 128;
        for (int i = threadIdx.x; i < 128 * GA; i += 256)
            sm[i] = V[(size_t)j0 * GA + i];
        __syncthreads();
        for (int i = threadIdx.x; i < 128 * GA; i += 256) {
            int a = i >> 7, j = i & 127;
            float f = sm[j * GA + a];
            __nv_bfloat16 h = __float2bfloat16(f);
            __nv_bfloat16 lo = __float2bfloat16(f - __bfloat162float(h));
            g_VThi[(size_t)a * NH + j0 + j] = h;
            g_VTlo[(size_t)a * NH + j0 + j] = lo;
        }
        return;
    }
    int idx = (blockIdx.x - 128) * 256 + threadIdx.x;
    float f;
    __nv_bfloat16* dh;
    __nv_bfloat16* dl;
    int d;
    if (idx < NK * HID * SDIM) {
        int k = idx / (HID * SDIM), r = idx % (HID * SDIM);
        int o = r / SDIM, i = r % SDIM;
        f = W0[((size_t)k * SDIM + i) * HID + o];
        dh = g_W0Thi; dl = g_W0Tlo; d = idx;
    } else if (idx < NK * HID * SDIM + NK * HID * HID) {
        int x = idx - NK * HID * SDIM;
        int k = x / (HID * HID), r = x % (HID * HID);
        int o = r / HID, i = r % HID;
        f = W1[((size_t)k * HID + i) * HID + o];
        dh = g_W1Thi; dl = g_W1Tlo; d = x;
    } else if (idx < NK * HID * SDIM + 2 * NK * HID * HID) {
        int x = idx - NK * HID * SDIM - NK * HID * HID;
        int k = x / (HID * HID), r = x % (HID * HID);
        int o = r / HID, i = r % HID;
        f = W2[((size_t)k * HID + i) * HID + o];
        dh = g_W2Thi; dl = g_W2Tlo; d = x;
    } else return;
    __nv_bfloat16 h = __float2bfloat16(f);
    dh[d] = h;
    dl[d] = __float2bfloat16(f - __bfloat162float(h));
}

// ---------------------------------------------------------------------------
// Unified encoder on tensor cores: 3x (Linear+ReLU), 3-pass bf16 error-split.
// Grid (136, NK): blocks [0,128) = history (emit Khi/Klo + norms),
// blocks [128,136) = state (emit fp32 g_enc_s). 256 threads.
// ---------------------------------------------------------------------------
__global__ __launch_bounds__(256) void encoder_k_kernel(
    const float* __restrict__ hist, const float* __restrict__ state,
    const float* __restrict__ b0, const float* __restrict__ b1,
    const float* __restrict__ b2)
{
    extern __shared__ char esm[];
    const uint32_t sb = (uint32_t)__cvta_generic_to_shared(esm);
    const int tid  = threadIdx.x;
    const int warp = tid >> 5;
    const int lane = tid & 31;
    const int k    = blockIdx.y;
    const int mode = (blockIdx.x < 128) ? 1 : 0;
    const int row0 = mode ? blockIdx.x * 128 : (blockIdx.x - 128) * 128;
    const float* x = mode ? hist : state;

    // X0: 128 rows x 32 cols fp32 -> bf16 hi/lo smem
    #pragma unroll
    for (int it = 0; it < 16; it++) {
        int idx = tid + it * 256;
        int row = idx >> 5, c = idx & 31;
        float f = x[(size_t)(row0 + row) * SDIM + c];
        __nv_bfloat16 h = __float2bfloat16(f);
        *(__nv_bfloat16*)(esm + E_XH + row * EROWB + c * 2) = h;
        *(__nv_bfloat16*)(esm + E_XL + row * EROWB + c * 2) =
            __float2bfloat16(f - __bfloat162float(h));
    }
    // W0T: 64 rows x 32 bf16 (64B) via cp.async
    {
        int row = tid >> 2, c = tid & 3;
        cp16(sb + E_WH + row * EROWB + c * 16,
             g_W0Thi + ((size_t)k * HID + row) * SDIM + c * 8);
        cp16(sb + E_WL + row * EROWB + c * 16,
             g_W0Tlo + ((size_t)k * HID + row) * SDIM + c * 8);
    }
    CP_COMMIT();
    CP_WAIT(0);
    __syncthreads();

    const uint32_t aro  = (16 * warp + (lane & 15)) * EROWB;
    const uint32_t asel = ((lane >> 4) & 1) * 8;
    const uint32_t lr8  = lane & 7, lc8 = (lane >> 3) & 3;
    const int r = lane >> 2, tq = lane & 3;
    const int wrow = 16 * warp + r;

    float acc[8][4];

    // ---- layer 0 (K=32) ----
    #pragma unroll
    for (int n = 0; n < 8; n++)
        #pragma unroll
        for (int e = 0; e < 4; e++) acc[n][e] = 0.f;
    {
        uint32_t ah[2][4], al[2][4];
        #pragma unroll
        for (int kf = 0; kf < 2; kf++) {
            ldsm4(ah[kf], sb + E_XH + aro + (kf * 16 + asel) * 2);
            ldsm4(al[kf], sb + E_XL + aro + (kf * 16 + asel) * 2);
        }
        const uint32_t co = (lc8 * 8) * 2;
        #pragma unroll
        for (int n = 0; n < 8; n++) {
            uint32_t bh[4], bl[4];
            ldsm4(bh, sb + E_WH + (n * 8 + lr8) * EROWB + co);
            ldsm4(bl, sb + E_WL + (n * 8 + lr8) * EROWB + co);
            mma16816(acc[n], ah[0], bh[0], bh[1]);
            mma16816(acc[n], ah[1], bh[2], bh[3]);
            mma16816(acc[n], al[0], bh[0], bh[1]);
            mma16816(acc[n], al[1], bh[2], bh[3]);
            mma16816(acc[n], ah[0], bl[0], bl[1]);
            mma16816(acc[n], ah[1], bl[2], bl[3]);
        }
    }
    __syncthreads();   // all layer-0 reads complete

    // bias+ReLU+split -> X smem; load W1
    {
        const float* bp = b0 + k * HID;
        #pragma unroll
        for (int n = 0; n < 8; n++) {
            int col = n * 8 + tq * 2;
            float ba = __ldg(bp + col), bb = __ldg(bp + col + 1);
            float h0 = fmaxf(acc[n][0] + ba, 0.f);
            float h1 = fmaxf(acc[n][1] + bb, 0.f);
            float h2 = fmaxf(acc[n][2] + ba, 0.f);
            float h3 = fmaxf(acc[n][3] + bb, 0.f);
            uint32_t w01 = packbf(h1, h0), w23 = packbf(h3, h2);
            float r0 = h0 - __uint_as_float(w01 << 16);
            float r1 = h1 - __uint_as_float(w01 & 0xffff0000u);
            float r2 = h2 - __uint_as_float(w23 << 16);
            float r3 = h3 - __uint_as_float(w23 & 0xffff0000u);
            *(uint32_t*)(esm + E_XH + wrow * EROWB + col * 2)       = w01;
            *(uint32_t*)(esm + E_XH + (wrow + 8) * EROWB + col * 2) = w23;
            *(uint32_t*)(esm + E_XL + wrow * EROWB + col * 2)       = packbf(r1, r0);
            *(uint32_t*)(esm + E_XL + (wrow + 8) * EROWB + col * 2) = packbf(r3, r2);
        }
        #pragma unroll
        for (int it = 0; it < 2; it++) {
            int idx = tid + it * 256;
            int row = idx >> 3, c = idx & 7;
            cp16(sb + E_WH + row * EROWB + c * 16,
                 g_W1Thi + ((size_t)k * HID + row) * HID + c * 8);
            cp16(sb + E_WL + row * EROWB + c * 16,
                 g_W1Tlo + ((size_t)k * HID + row) * HID + c * 8);
        }
        CP_COMMIT();
        CP_WAIT(0);
        __syncthreads();
    }

    // ---- layers 1 & 2 (K=64) ----
    #pragma unroll
    for (int layer = 1; layer <= 2; layer++) {
        #pragma unroll
        for (int n = 0; n < 8; n++)
            #pragma unroll
            for (int e = 0; e < 4; e++) acc[n][e] = 0.f;
        uint32_t ah[4][4], al[4][4];
        #pragma unroll
        for (int kf = 0; kf < 4; kf++) {
            ldsm4(ah[kf], sb + E_XH + aro + (kf * 16 + asel) * 2);
            ldsm4(al[kf], sb + E_XL + aro + (kf * 16 + asel) * 2);
        }
        #pragma unroll
        for (int dp = 0; dp < 2; dp++) {
            const uint32_t co = (dp * 32 + lc8 * 8) * 2;
            const int k0 = 2 * dp, k1 = 2 * dp + 1;
            #pragma unroll
            for (int n = 0; n < 8; n++) {
                uint32_t bh[4], bl[4];
                ldsm4(bh, sb + E_WH + (n * 8 + lr8) * EROWB + co);
                ldsm4(bl, sb + E_WL + (n * 8 + lr8) * EROWB + co);
                mma16816(acc[n], ah[k0], bh[0], bh[1]);
                mma16816(acc[n], ah[k1], bh[2], bh[3]);
                mma16816(acc[n], al[k0], bh[0], bh[1]);
                mma16816(acc[n], al[k1], bh[2], bh[3]);
                mma16816(acc[n], ah[k0], bl[0], bl[1]);
                mma16816(acc[n], ah[k1], bl[2], bl[3]);
            }
        }
        __syncthreads();

        if (layer == 1) {
            const float* bp = b1 + k * HID;
            #pragma unroll
            for (int n = 0; n < 8; n++) {
                int col = n * 8 + tq * 2;
                float ba = __ldg(bp + col), bb = __ldg(bp + col + 1);
                float h0 = fmaxf(acc[n][0] + ba, 0.f);
                float h1 = fmaxf(acc[n][1] + bb, 0.f);
                float h2 = fmaxf(acc[n][2] + ba, 0.f);
                float h3 = fmaxf(acc[n][3] + bb, 0.f);
                uint32_t w01 = packbf(h1, h0), w23 = packbf(h3, h2);
                float r0 = h0 - __uint_as_float(w01 << 16);
                float r1 = h1 - __uint_as_float(w01 & 0xffff0000u);
                float r2 = h2 - __uint_as_float(w23 << 16);
                float r3 = h3 - __uint_as_float(w23 & 0xffff0000u);
                *(uint32_t*)(esm + E_XH + wrow * EROWB + col * 2)       = w01;
                *(uint32_t*)(esm + E_XH + (wrow + 8) * EROWB + col * 2) = w23;
                *(uint32_t*)(esm + E_XL + wrow * EROWB + col * 2)       = packbf(r1, r0);
                *(uint32_t*)(esm + E_XL + (wrow + 8) * EROWB + col * 2) = packbf(r3, r2);
            }
            #pragma unroll
            for (int it = 0; it < 2; it++) {
                int idx = tid + it * 256;
                int row = idx >> 3, c = idx & 7;
                cp16(sb + E_WH + row * EROWB + c * 16,
                     g_W2Thi + ((size_t)k * HID + row) * HID + c * 8);
                cp16(sb + E_WL + row * EROWB + c * 16,
                     g_W2Tlo + ((size_t)k * HID + row) * HID + c * 8);
            }
            CP_COMMIT();
            CP_WAIT(0);
            __syncthreads();
        } else if (mode == 1) {
            // final: write g_Khi/g_Klo + row norms
            const float* bp = b2 + k * HID;
            const size_t ga = (size_t)k * NH + row0 + wrow;
            float sA = 0.f, sB = 0.f;
            #pragma unroll
            for (int n = 0; n < 8; n++) {
                int col = n * 8 + tq * 2;
                float ba = __ldg(bp + col), bb = __ldg(bp + col + 1);
                float h0 = fmaxf(acc[n][0] + ba, 0.f);
                float h1 = fmaxf(acc[n][1] + bb, 0.f);
                float h2 = fmaxf(acc[n][2] + ba, 0.f);
                float h3 = fmaxf(acc[n][3] + bb, 0.f);
                sA += h0 * h0 + h1 * h1;
                sB += h2 * h2 + h3 * h3;
                uint32_t w01 = packbf(h1, h0), w23 = packbf(h3, h2);
                float r0 = h0 - __uint_as_float(w01 << 16);
                float r1 = h1 - __uint_as_float(w01 & 0xffff0000u);
                float r2 = h2 - __uint_as_float(w23 << 16);
                float r3 = h3 - __uint_as_float(w23 & 0xffff0000u);
                *(uint32_t*)((__nv_bfloat16*)g_Khi + ga * HID + col)       = w01;
                *(uint32_t*)((__nv_bfloat16*)g_Khi + (ga + 8) * HID + col) = w23;
                *(uint32_t*)((__nv_bfloat16*)g_Klo + ga * HID + col)       = packbf(r1, r0);
                *(uint32_t*)((__nv_bfloat16*)g_Klo + (ga + 8) * HID + col) = packbf(r3, r2);
            }
            sA += __shfl_xor_sync(0xffffffffu, sA, 1);
            sA += __shfl_xor_sync(0xffffffffu, sA, 2);
            sB += __shfl_xor_sync(0xffffffffu, sB, 1);
            sB += __shfl_xor_sync(0xffffffffu, sB, 2);
            if (tq == 0) {
                float mx = fmaxf(sqrtf(sA), sqrtf(sB));
                atomicMax((int*)&g_Kmax[k], __float_as_int(mx));
            }
        } else {
            // final: write fp32 g_enc_s (state encoder)
            const float* bp = b2 + k * HID;
            const size_t base = ((size_t)k * NB + row0 + wrow) * HID;
            #pragma unroll
            for (int n = 0; n < 8; n++) {
                int col = n * 8 + tq * 2;
                float ba = __ldg(bp + col), bb = __ldg(bp + col + 1);
                g_enc_s[base + col]               = fmaxf(acc[n][0] + ba, 0.f);
                g_enc_s[base + col + 1]           = fmaxf(acc[n][1] + bb, 0.f);
                g_enc_s[base + 8 * HID + col]     = fmaxf(acc[n][2] + ba, 0.f);
                g_enc_s[base + 8 * HID + col + 1] = fmaxf(acc[n][3] + bb, 0.f);
            }
        }
    }
}

// ---------------------------------------------------------------------------
// mma.sync flash attention. Grid (4, NK, NSPLIT), 512 thr. Warp-phase
// staggered: warps 8-15 process key-halves in reverse order so each SMSP
// always has warps in the MMA phase while others run exp/pack.
// ---------------------------------------------------------------------------
__device__ __forceinline__ void load_tile(uint32_t sb, int k, int key0, int buf,
                                          int tid)
{
    const uint32_t kh = sb + (buf ? SM_KH1 : SM_KH0);
    const uint32_t kl = sb + (buf ? SM_KL1 : SM_KL0);
    const char* shi = (const char*)(g_Khi + ((size_t)k * NH + key0) * HID);
    const char* slo = (const char*)(g_Klo + ((size_t)k * NH + key0) * HID);
    #pragma unroll
    for (int it = 0; it < 2; it++) {
        int idx = tid + it * ATHR;              // 0..1023
        int row = idx >> 3, c = idx & 7;
        uint32_t doff = row * KROWB + c * 16;
        size_t goff = (size_t)row * 128 + c * 16;
        cp16(kh + doff, shi + goff);
        cp16(kl + doff, slo + goff);
    }
    const uint32_t vh = sb + (buf ? SM_VH1 : SM_VH0);
    const uint32_t vl = sb + (buf ? SM_VL1 : SM_VL0);
    const char* vhi = (const char*)g_VThi + (size_t)key0 * 2;
    const char* vlo = (const char*)g_VTlo + (size_t)key0 * 2;
    #pragma unroll
    for (int it = 0; it < 3; it++) {
        int idx = tid + it * ATHR;              // 0..1535, need 1280
        if (idx < 1280) {
            int a = idx >> 4, c = idx & 15;
            uint32_t doff = a * VROWB + c * 16;
            size_t goff = (size_t)a * NH * 2 + c * 16;
            cp16(vh + doff, vhi + goff);
            cp16(vl + doff, vlo + goff);
        }
    }
}

__global__ __launch_bounds__(ATHR, 1) void attn_kernel()
{
    extern __shared__ char smem[];
    const uint32_t sb = (uint32_t)__cvta_generic_to_shared(smem);
    const int tid  = threadIdx.x;
    const int warp = tid >> 5;
    const int lane = tid & 31;
    const int k    = blockIdx.y;
    const int sp   = blockIdx.z;
    const int q0   = blockIdx.x * MQ;
    const int kb0  = sp * KEYS_PER_CTA;

    const float* Qg = g_enc_s + ((size_t)k * NB + q0) * HID;
    float* MH = (float*)(smem + SM_MHAT);

    // m-hat per query row (fixed softmax bound)
    if (tid < MQ) {
        const float4* qr = (const float4*)(Qg + tid * HID);
        float ss = 0.f;
        #pragma unroll
        for (int i = 0; i < 16; i++) {
            float4 f = qr[i];
            ss += f.x * f.x + f.y * f.y + f.z * f.z + f.w * f.w;
        }
        MH[tid] = sqrtf(ss) * g_Kmax[k];
    }

    // stage Q: hi into SM_QHI (aliases K buf0, 256 rows), lo into SM_QLO
    {
        int row = tid >> 1, half = tid & 1;
        const float* qr = Qg + row * HID + half * 32;
        char* dh = smem + SM_QHI + row * KROWB + half * 64;
        char* dl = smem + SM_QLO + row * KROWB + half * 64;
        #pragma unroll
        for (int i = 0; i < 8; i++) {
            float4 f = *(const float4*)(qr + i * 4);
            uint32_t h0 = packbf(f.y, f.x);
            uint32_t h1 = packbf(f.w, f.z);
            float r0 = f.x - __uint_as_float(h0 << 16);
            float r1 = f.y - __uint_as_float(h0 & 0xffff0000u);
            float r2 = f.z - __uint_as_float(h1 << 16);
            float r3 = f.w - __uint_as_float(h1 & 0xffff0000u);
            *(uint32_t*)(dh + i * 8)     = h0;
            *(uint32_t*)(dh + i * 8 + 4) = h1;
            *(uint32_t*)(dl + i * 8)     = packbf(r1, r0);
            *(uint32_t*)(dl + i * 8 + 4) = packbf(r3, r2);
        }
    }
    __syncthreads();

    // Q-hi fragments to registers (Q-lo stays resident in SM_QLO)
    uint32_t qh[4][4];
    const uint32_t qro = (16 * warp + (lane & 15)) * KROWB;
    const uint32_t qsel = ((lane >> 4) & 1) * 8;
    #pragma unroll
    for (int kk = 0; kk < 4; kk++)
        ldsm4(qh[kk], sb + SM_QHI + qro + (kk * 16 + qsel) * 2);
    const float mh0 = MH[16 * warp + (lane >> 2)];
    const float mh1 = MH[16 * warp + (lane >> 2) + 8];
    __syncthreads();   // Q-hi staging area now free for K tiles

    load_tile(sb, k, kb0, 0, tid);
    CP_COMMIT();

    float oacc[10][4];
    #pragma unroll
    for (int ab = 0; ab < 10; ab++)
        #pragma unroll
        for (int e = 0; e < 4; e++) oacc[ab][e] = 0.f;
    float lacc0 = 0.f, lacc1 = 0.f;

    const uint32_t lr8 = (lane & 7), lc8 = ((lane >> 3) & 3);
    const int hswap = (warp >> 3) & 1;   // warps 8-15 reverse half order

    for (int t = 0; t < TILES; t++) {
        if (t + 1 < TILES) {
            load_tile(sb, k, kb0 + (t + 1) * KT, (t + 1) & 1, tid);
            CP_COMMIT();
            CP_WAIT(1);
        } else {
            CP_WAIT(0);
        }
        __syncthreads();

        const uint32_t KH = sb + ((t & 1) ? SM_KH1 : SM_KH0);
        const uint32_t KL = sb + ((t & 1) ? SM_KL1 : SM_KL0);
        const uint32_t VH = sb + ((t & 1) ? SM_VH1 : SM_VH0);
        const uint32_t VL = sb + ((t & 1) ? SM_VL1 : SM_VL0);

        #pragma unroll
        for (int hfi = 0; hfi < 2; hfi++) {
            const int hf = hswap ? (1 - hfi) : hfi;
            // ---- scores for 64-key half: S = QhiKhi + QloKhi + QhiKlo ----
            float sacc[8][4];
            #pragma unroll
            for (int nb = 0; nb < 8; nb++)
                #pragma unroll
                for (int e = 0; e < 4; e++) sacc[nb][e] = 0.f;

            #pragma unroll
            for (int dp = 0; dp < 2; dp++) {
                uint32_t qlA[4], qlB[4];
                ldsm4(qlA, sb + SM_QLO + qro + ((2 * dp) * 16 + qsel) * 2);
                ldsm4(qlB, sb + SM_QLO + qro + ((2 * dp + 1) * 16 + qsel) * 2);
                const uint32_t co = (dp * 32 + lc8 * 8) * 2;
                const int k0 = 2 * dp, k1 = 2 * dp + 1;
                #pragma unroll
                for (int nb2 = 0; nb2 < 4; nb2++) {
                    const int n0 = hf * 8 + 2 * nb2, n1 = n0 + 1;
                    const int l0 = 2 * nb2, l1 = l0 + 1;
                    uint32_t bh0[4], bl0[4], bh1[4], bl1[4];
                    ldsm4(bh0, KH + (n0 * 8 + lr8) * KROWB + co);
                    ldsm4(bh1, KH + (n1 * 8 + lr8) * KROWB + co);
                    ldsm4(bl0, KL + (n0 * 8 + lr8) * KROWB + co);
                    ldsm4(bl1, KL + (n1 * 8 + lr8) * KROWB + co);
                    mma16816(sacc[l0], qh[k0], bh0[0], bh0[1]);
                    mma16816(sacc[l1], qh[k0], bh1[0], bh1[1]);
                    mma16816(sacc[l0], qh[k1], bh0[2], bh0[3]);
                    mma16816(sacc[l1], qh[k1], bh1[2], bh1[3]);
                    mma16816(sacc[l0], qlA, bh0[0], bh0[1]);
                    mma16816(sacc[l1], qlA, bh1[0], bh1[1]);
                    mma16816(sacc[l0], qlB, bh0[2], bh0[3]);
                    mma16816(sacc[l1], qlB, bh1[2], bh1[3]);
                    mma16816(sacc[l0], qh[k0], bl0[0], bl0[1]);
                    mma16816(sacc[l1], qh[k0], bl1[0], bl1[1]);
                    mma16816(sacc[l0], qh[k1], bl0[2], bl0[3]);
                    mma16816(sacc[l1], qh[k1], bl1[2], bl1[3]);
                }
            }

            // ---- softmax with fixed bound ----
            #pragma unroll
            for (int nb = 0; nb < 8; nb++) {
                float p0 = __expf(sacc[nb][0] - mh0);
                float p1 = __expf(sacc[nb][1] - mh0);
                float p2 = __expf(sacc[nb][2] - mh1);
                float p3 = __expf(sacc[nb][3] - mh1);
                lacc0 += p0 + p1;
                lacc1 += p2 + p3;
                sacc[nb][0] = p0; sacc[nb][1] = p1;
                sacc[nb][2] = p2; sacc[nb][3] = p3;
            }

            // ---- PV over this key half: O += PhiVhi + PloVhi + PhiVlo ----
            #pragma unroll
            for (int jp = 0; jp < 2; jp++) {
                uint32_t ah[2][4], al[2][4];
                #pragma unroll
                for (int m = 0; m < 2; m++) {
                    const int nA = 4 * jp + 2 * m;
                    #pragma unroll
                    for (int h = 0; h < 2; h++) {
                        float c0 = sacc[nA + h][0], c1 = sacc[nA + h][1];
                        float c2 = sacc[nA + h][2], c3 = sacc[nA + h][3];
                        uint32_t h01 = packbf(c1, c0);
                        uint32_t h23 = packbf(c3, c2);
                        ah[m][2 * h]     = h01;
                        ah[m][2 * h + 1] = h23;
                        float r0 = c0 - __uint_as_float(h01 << 16);
                        float r1 = c1 - __uint_as_float(h01 & 0xffff0000u);
                        float r2 = c2 - __uint_as_float(h23 << 16);
                        float r3 = c3 - __uint_as_float(h23 & 0xffff0000u);
                        al[m][2 * h]     = packbf(r1, r0);
                        al[m][2 * h + 1] = packbf(r3, r2);
                    }
                }
                const uint32_t co = ((hf * 2 + jp) * 32 + lc8 * 8) * 2;
                #pragma unroll
                for (int ab2 = 0; ab2 < 5; ab2++) {
                    const int a0 = 2 * ab2, a1 = a0 + 1;
                    uint32_t vh0[4], vh1[4], vl0[4], vl1[4];
                    ldsm4(vh0, VH + (a0 * 8 + lr8) * VROWB + co);
                    ldsm4(vh1, VH + (a1 * 8 + lr8) * VROWB + co);
                    mma16816(oacc[a0], ah[0], vh0[0], vh0[1]);
                    mma16816(oacc[a1], ah[0], vh1[0], vh1[1]);
                    mma16816(oacc[a0], ah[1], vh0[2], vh0[3]);
                    mma16816(oacc[a1], ah[1], vh1[2], vh1[3]);
                    mma16816(oacc[a0], al[0], vh0[0], vh0[1]);
                    mma16816(oacc[a1], al[0], vh1[0], vh1[1]);
                    mma16816(oacc[a0], al[1], vh0[2], vh0[3]);
                    mma16816(oacc[a1], al[1], vh1[2], vh1[3]);
                    ldsm4(vl0, VL + (a0 * 8 + lr8) * VROWB + co);
                    ldsm4(vl1, VL + (a1 * 8 + lr8) * VROWB + co);
                    mma16816(oacc[a0], ah[0], vl0[0], vl0[1]);
                    mma16816(oacc[a1], ah[0], vl1[0], vl1[1]);
                    mma16816(oacc[a0], ah[1], vl0[2], vl0[3]);
                    mma16816(oacc[a1], ah[1], vl1[2], vl1[3]);
                }
            }
        }
        __syncthreads();
    }

    // ---- epilogue: write unnormalized O + l ----
    const int r  = lane >> 2, tq = lane & 3;
    const int qrow0 = q0 + 16 * warp + r;
    const int qrow1 = qrow0 + 8;
    float* Ob = g_Opart + ((size_t)sp * NK + k) * NB * GA;
    #pragma unroll
    for (int ab = 0; ab < 10; ab++) {
        const int col = ab * 8 + tq * 2;
        Ob[(size_t)qrow0 * GA + col]     = oacc[ab][0];
        Ob[(size_t)qrow0 * GA + col + 1] = oacc[ab][1];
        Ob[(size_t)qrow1 * GA + col]     = oacc[ab][2];
        Ob[(size_t)qrow1 * GA + col + 1] = oacc[ab][3];
    }
    lacc0 += __shfl_xor_sync(0xffffffffu, lacc0, 1);
    lacc0 += __shfl_xor_sync(0xffffffffu, lacc0, 2);
    lacc1 += __shfl_xor_sync(0xffffffffu, lacc1, 1);
    lacc1 += __shfl_xor_sync(0xffffffffu, lacc1, 2);
    if (tq == 0) {
        float* Lb = g_lsum + ((size_t)sp * NK + k) * NB;
        Lb[qrow0] = lacc0;
        Lb[qrow1] = lacc1;
    }
}

// ---------------------------------------------------------------------------
// Merge: sum splits (shared m-hat => plain sums), normalize, k-combine.
// ---------------------------------------------------------------------------
__global__ __launch_bounds__(256) void merge_kernel(
    const float* __restrict__ assign, float* __restrict__ out)
{
    int idx = blockIdx.x * 256 + threadIdx.x;
    if (idx >= NB * GA) return;
    int b  = idx / GA;
    int ga = idx - b * GA;
    int g  = ga >> 3;

    float aw[NK], mxw = -CUDART_INF_F;
    #pragma unroll
    for (int k = 0; k < NK; k++) {
        aw[k] = __ldg(assign + g * NK + k);
        mxw = fmaxf(mxw, aw[k]);
    }
    float wsum = 0.f;
    #pragma unroll
    for (int k = 0; k < NK; k++) { aw[k] = __expf(aw[k] - mxw); wsum += aw[k]; }
    float winv = 1.f / wsum;

    float acc = 0.f;
    #pragma unroll
    for (int k = 0; k < NK; k++) {
        float O = 0.f, L = 0.f;
        #pragma unroll
        for (int s = 0; s < NSPLIT; s++) {
            O += g_Opart[(((size_t)s * NK + k) * NB + b) * GA + ga];
            L += g_lsum[((size_t)s * NK + k) * NB + b];
        }
        acc += aw[k] * (O / L);
    }
    out[idx] = acc * winv;
}

// ---------------------------------------------------------------------------
extern "C" void kernel_launch(void* const* d_in, const int* in_sizes, int n_in,
                              void* d_out, int out_size)
{
    (void)in_sizes; (void)n_in; (void)out_size;
    const float* state  = (const float*)d_in[0];
    const float* hist   = (const float*)d_in[1];
    const float* jah    = (const float*)d_in[2];
    const float* W0 = (const float*)d_in[3];
    const float* b0 = (const float*)d_in[4];
    const float* W1 = (const float*)d_in[5];
    const float* b1 = (const float*)d_in[6];
    const float* W2 = (const float*)d_in[7];
    const float* b2 = (const float*)d_in[8];
    const float* assign = (const float*)d_in[9];
    float* out = (float*)d_out;

    prep_kernel<<<288, 256>>>(jah, W0, W1, W2);

    cudaFuncSetAttribute(encoder_k_kernel,
                         cudaFuncAttributeMaxDynamicSharedMemorySize, E_TOTAL);
    encoder_k_kernel<<<dim3(136, NK), 256, E_TOTAL>>>(hist, state, b0, b1, b2);

    cudaFuncSetAttribute(attn_kernel,
                         cudaFuncAttributeMaxDynamicSharedMemorySize, SM_TOTAL);
    attn_kernel<<<dim3(NB / MQ, NK, NSPLIT), ATHR, SM_TOTAL>>>();

    merge_kernel<<<(NB * GA + 255) / 256, 256>>>(assign, out);
}

// round 16
// speedup vs baseline: 1.6262x; 1.0105x over previous
#include <cuda_runtime.h>
#include <cuda_bf16.h>
#include <math_constants.h>
#include <cstdint>

#define NB   1024
#define NH   16384
#define SDIM 32
#define HID  64
#define NK   4
#define GA   80

#define MQ   256
#define KT   128
#define NSPLIT 8
#define KEYS_PER_CTA (NH / NSPLIT)   // 2048
#define TILES (KEYS_PER_CTA / KT)    // 16
#define ATHR 512

#define KROWB 144    // K/Q smem row stride bytes (64 bf16 + 16B pad)
#define VROWB 272    // V smem row stride bytes (128 bf16 + 16B pad)

// attn smem byte offsets
#define SM_MHAT 0                            // 256 floats
#define SM_QLO  1024                         // 256 * KROWB = 36864
#define SM_KH0  (SM_QLO + 256 * KROWB)       // 37888
#define SM_QHI  SM_KH0                       // Q-hi staging aliases KH0+KL0 (256 rows)
#define SM_KL0  (SM_KH0 + 128 * KROWB)       // 56320
#define SM_KH1  (SM_KL0 + 128 * KROWB)       // 74752
#define SM_KL1  (SM_KH1 + 128 * KROWB)       // 93184
#define SM_VH0  (SM_KL1 + 128 * KROWB)       // 111616
#define SM_VL0  (SM_VH0 + 80 * VROWB)        // 133376
#define SM_VH1  (SM_VL0 + 80 * VROWB)        // 155136
#define SM_VL1  (SM_VH1 + 80 * VROWB)        // 176896
#define SM_TOTAL (SM_VL1 + 80 * VROWB)       // 198656

// encoder smem byte offsets
#define EROWB 144
#define E_XH  0
#define E_XL  18432
#define E_WH  36864
#define E_WL  46080
#define E_TOTAL 55296

// global scratch
__device__ float         g_enc_s[NK * NB * HID];
__device__ __nv_bfloat16 g_Khi[NK * NH * HID];
__device__ __nv_bfloat16 g_Klo[NK * NH * HID];
__device__ __nv_bfloat16 g_VThi[GA * NH];
__device__ __nv_bfloat16 g_VTlo[GA * NH];
__device__ float         g_Kmax[NK];
__device__ float         g_Oacc[NK * NB * GA];   // atomically accumulated O
__device__ float         g_lacc[NK * NB];        // atomically accumulated l
// transposed + bf16-split weights [k][out][in]
__device__ __nv_bfloat16 g_W0Thi[NK * HID * SDIM];
__device__ __nv_bfloat16 g_W0Tlo[NK * HID * SDIM];
__device__ __nv_bfloat16 g_W1Thi[NK * HID * HID];
__device__ __nv_bfloat16 g_W1Tlo[NK * HID * HID];
__device__ __nv_bfloat16 g_W2Thi[NK * HID * HID];
__device__ __nv_bfloat16 g_W2Tlo[NK * HID * HID];

// ---------------- helpers ----------------
__device__ __forceinline__ void cp16(uint32_t sdst, const void* gsrc) {
    asm volatile("cp.async.cg.shared.global [%0], [%1], 16;" :: "r"(sdst), "l"(gsrc));
}
#define CP_COMMIT() asm volatile("cp.async.commit_group;" ::: "memory")
#define CP_WAIT(n)  asm volatile("cp.async.wait_group %0;" :: "n"(n) : "memory")

__device__ __forceinline__ void ldsm4(uint32_t* r, uint32_t addr) {
    asm volatile("ldmatrix.sync.aligned.m8n8.x4.shared.b16 {%0,%1,%2,%3}, [%4];"
        : "=r"(r[0]), "=r"(r[1]), "=r"(r[2]), "=r"(r[3]) : "r"(addr));
}
__device__ __forceinline__ void mma16816(float* d, const uint32_t* a,
                                         uint32_t b0, uint32_t b1) {
    asm volatile("mma.sync.aligned.m16n8k16.row.col.f32.bf16.bf16.f32 "
        "{%0,%1,%2,%3}, {%4,%5,%6,%7}, {%8,%9}, {%0,%1,%2,%3};"
        : "+f"(d[0]), "+f"(d[1]), "+f"(d[2]), "+f"(d[3])
        : "r"(a[0]), "r"(a[1]), "r"(a[2]), "r"(a[3]), "r"(b0), "r"(b1));
}
__device__ __forceinline__ uint32_t packbf(float hi, float lo) {
    uint32_t r;
    asm("cvt.rn.bf16x2.f32 %0, %1, %2;" : "=r"(r) : "f"(hi), "f"(lo));
    return r;
}

// ---------------------------------------------------------------------------
// Prep: blocks [0,128) V transpose+split; [128,288) weight prep;
// [288,416) zero the atomic accumulators.
// ---------------------------------------------------------------------------
__global__ __launch_bounds__(256) void prep_kernel(
    const float* __restrict__ V,
    const float* __restrict__ W0, const float* __restrict__ W1,
    const float* __restrict__ W2)
{
    __shared__ float sm[128 * GA];
    if (blockIdx.x < 128) {
        const int j0 = blockIdx.x * 128;
        for (int i = threadIdx.x; i < 128 * GA; i += 256)
            sm[i] = V[(size_t)j0 * GA + i];
        __syncthreads();
        for (int i = threadIdx.x; i < 128 * GA; i += 256) {
            int a = i >> 7, j = i & 127;
            float f = sm[j * GA + a];
            __nv_bfloat16 h = __float2bfloat16(f);
            __nv_bfloat16 lo = __float2bfloat16(f - __bfloat162float(h));
            g_VThi[(size_t)a * NH + j0 + j] = h;
            g_VTlo[(size_t)a * NH + j0 + j] = lo;
        }
        return;
    }
    if (blockIdx.x >= 288) {
        const int nO = NK * NB * GA;
        for (int i = (blockIdx.x - 288) * 256 + threadIdx.x;
             i < nO; i += 128 * 256)
            g_Oacc[i] = 0.f;
        int i2 = (blockIdx.x - 288) * 256 + threadIdx.x;
        if (i2 < NK * NB) g_lacc[i2] = 0.f;
        return;
    }
    int idx = (blockIdx.x - 128) * 256 + threadIdx.x;
    float f;
    __nv_bfloat16* dh;
    __nv_bfloat16* dl;
    int d;
    if (idx < NK * HID * SDIM) {
        int k = idx / (HID * SDIM), r = idx % (HID * SDIM);
        int o = r / SDIM, i = r % SDIM;
        f = W0[((size_t)k * SDIM + i) * HID + o];
        dh = g_W0Thi; dl = g_W0Tlo; d = idx;
    } else if (idx < NK * HID * SDIM + NK * HID * HID) {
        int x = idx - NK * HID * SDIM;
        int k = x / (HID * HID), r = x % (HID * HID);
        int o = r / HID, i = r % HID;
        f = W1[((size_t)k * HID + i) * HID + o];
        dh = g_W1Thi; dl = g_W1Tlo; d = x;
    } else if (idx < NK * HID * SDIM + 2 * NK * HID * HID) {
        int x = idx - NK * HID * SDIM - NK * HID * HID;
        int k = x / (HID * HID), r = x % (HID * HID);
        int o = r / HID, i = r % HID;
        f = W2[((size_t)k * HID + i) * HID + o];
        dh = g_W2Thi; dl = g_W2Tlo; d = x;
    } else return;
    __nv_bfloat16 h = __float2bfloat16(f);
    dh[d] = h;
    dl[d] = __float2bfloat16(f - __bfloat162float(h));
}

// ---------------------------------------------------------------------------
// Unified encoder on tensor cores: 3x (Linear+ReLU), 3-pass bf16 error-split.
// Grid (136, NK): blocks [0,128) = history (emit Khi/Klo + norms),
// blocks [128,136) = state (emit fp32 g_enc_s). 256 threads.
// ---------------------------------------------------------------------------
__global__ __launch_bounds__(256) void encoder_k_kernel(
    const float* __restrict__ hist, const float* __restrict__ state,
    const float* __restrict__ b0, const float* __restrict__ b1,
    const float* __restrict__ b2)
{
    extern __shared__ char esm[];
    const uint32_t sb = (uint32_t)__cvta_generic_to_shared(esm);
    const int tid  = threadIdx.x;
    const int warp = tid >> 5;
    const int lane = tid & 31;
    const int k    = blockIdx.y;
    const int mode = (blockIdx.x < 128) ? 1 : 0;
    const int row0 = mode ? blockIdx.x * 128 : (blockIdx.x - 128) * 128;
    const float* x = mode ? hist : state;

    // X0: 128 rows x 32 cols fp32 -> bf16 hi/lo smem
    #pragma unroll
    for (int it = 0; it < 16; it++) {
        int idx = tid + it * 256;
        int row = idx >> 5, c = idx & 31;
        float f = x[(size_t)(row0 + row) * SDIM + c];
        __nv_bfloat16 h = __float2bfloat16(f);
        *(__nv_bfloat16*)(esm + E_XH + row * EROWB + c * 2) = h;
        *(__nv_bfloat16*)(esm + E_XL + row * EROWB + c * 2) =
            __float2bfloat16(f - __bfloat162float(h));
    }
    // W0T: 64 rows x 32 bf16 (64B) via cp.async
    {
        int row = tid >> 2, c = tid & 3;
        cp16(sb + E_WH + row * EROWB + c * 16,
             g_W0Thi + ((size_t)k * HID + row) * SDIM + c * 8);
        cp16(sb + E_WL + row * EROWB + c * 16,
             g_W0Tlo + ((size_t)k * HID + row) * SDIM + c * 8);
    }
    CP_COMMIT();
    CP_WAIT(0);
    __syncthreads();

    const uint32_t aro  = (16 * warp + (lane & 15)) * EROWB;
    const uint32_t asel = ((lane >> 4) & 1) * 8;
    const uint32_t lr8  = lane & 7, lc8 = (lane >> 3) & 3;
    const int r = lane >> 2, tq = lane & 3;
    const int wrow = 16 * warp + r;

    float acc[8][4];

    // ---- layer 0 (K=32) ----
    #pragma unroll
    for (int n = 0; n < 8; n++)
        #pragma unroll
        for (int e = 0; e < 4; e++) acc[n][e] = 0.f;
    {
        uint32_t ah[2][4], al[2][4];
        #pragma unroll
        for (int kf = 0; kf < 2; kf++) {
            ldsm4(ah[kf], sb + E_XH + aro + (kf * 16 + asel) * 2);
            ldsm4(al[kf], sb + E_XL + aro + (kf * 16 + asel) * 2);
        }
        const uint32_t co = (lc8 * 8) * 2;
        #pragma unroll
        for (int n = 0; n < 8; n++) {
            uint32_t bh[4], bl[4];
            ldsm4(bh, sb + E_WH + (n * 8 + lr8) * EROWB + co);
            ldsm4(bl, sb + E_WL + (n * 8 + lr8) * EROWB + co);
            mma16816(acc[n], ah[0], bh[0], bh[1]);
            mma16816(acc[n], ah[1], bh[2], bh[3]);
            mma16816(acc[n], al[0], bh[0], bh[1]);
            mma16816(acc[n], al[1], bh[2], bh[3]);
            mma16816(acc[n], ah[0], bl[0], bl[1]);
            mma16816(acc[n], ah[1], bl[2], bl[3]);
        }
    }
    __syncthreads();   // all layer-0 reads complete

    // bias+ReLU+split -> X smem; load W1
    {
        const float* bp = b0 + k * HID;
        #pragma unroll
        for (int n = 0; n < 8; n++) {
            int col = n * 8 + tq * 2;
            float ba = __ldg(bp + col), bb = __ldg(bp + col + 1);
            float h0 = fmaxf(acc[n][0] + ba, 0.f);
            float h1 = fmaxf(acc[n][1] + bb, 0.f);
            float h2 = fmaxf(acc[n][2] + ba, 0.f);
            float h3 = fmaxf(acc[n][3] + bb, 0.f);
            uint32_t w01 = packbf(h1, h0), w23 = packbf(h3, h2);
            float r0 = h0 - __uint_as_float(w01 << 16);
            float r1 = h1 - __uint_as_float(w01 & 0xffff0000u);
            float r2 = h2 - __uint_as_float(w23 << 16);
            float r3 = h3 - __uint_as_float(w23 & 0xffff0000u);
            *(uint32_t*)(esm + E_XH + wrow * EROWB + col * 2)       = w01;
            *(uint32_t*)(esm + E_XH + (wrow + 8) * EROWB + col * 2) = w23;
            *(uint32_t*)(esm + E_XL + wrow * EROWB + col * 2)       = packbf(r1, r0);
            *(uint32_t*)(esm + E_XL + (wrow + 8) * EROWB + col * 2) = packbf(r3, r2);
        }
        #pragma unroll
        for (int it = 0; it < 2; it++) {
            int idx = tid + it * 256;
            int row = idx >> 3, c = idx & 7;
            cp16(sb + E_WH + row * EROWB + c * 16,
                 g_W1Thi + ((size_t)k * HID + row) * HID + c * 8);
            cp16(sb + E_WL + row * EROWB + c * 16,
                 g_W1Tlo + ((size_t)k * HID + row) * HID + c * 8);
        }
        CP_COMMIT();
        CP_WAIT(0);
        __syncthreads();
    }

    // ---- layers 1 & 2 (K=64) ----
    #pragma unroll
    for (int layer = 1; layer <= 2; layer++) {
        #pragma unroll
        for (int n = 0; n < 8; n++)
            #pragma unroll
            for (int e = 0; e < 4; e++) acc[n][e] = 0.f;
        uint32_t ah[4][4], al[4][4];
        #pragma unroll
        for (int kf = 0; kf < 4; kf++) {
            ldsm4(ah[kf], sb + E_XH + aro + (kf * 16 + asel) * 2);
            ldsm4(al[kf], sb + E_XL + aro + (kf * 16 + asel) * 2);
        }
        #pragma unroll
        for (int dp = 0; dp < 2; dp++) {
            const uint32_t co = (dp * 32 + lc8 * 8) * 2;
            const int k0 = 2 * dp, k1 = 2 * dp + 1;
            #pragma unroll
            for (int n = 0; n < 8; n++) {
                uint32_t bh[4], bl[4];
                ldsm4(bh, sb + E_WH + (n * 8 + lr8) * EROWB + co);
                ldsm4(bl, sb + E_WL + (n * 8 + lr8) * EROWB + co);
                mma16816(acc[n], ah[k0], bh[0], bh[1]);
                mma16816(acc[n], ah[k1], bh[2], bh[3]);
                mma16816(acc[n], al[k0], bh[0], bh[1]);
                mma16816(acc[n], al[k1], bh[2], bh[3]);
                mma16816(acc[n], ah[k0], bl[0], bl[1]);
                mma16816(acc[n], ah[k1], bl[2], bl[3]);
            }
        }
        __syncthreads();

        if (layer == 1) {
            const float* bp = b1 + k * HID;
            #pragma unroll
            for (int n = 0; n < 8; n++) {
                int col = n * 8 + tq * 2;
                float ba = __ldg(bp + col), bb = __ldg(bp + col + 1);
                float h0 = fmaxf(acc[n][0] + ba, 0.f);
                float h1 = fmaxf(acc[n][1] + bb, 0.f);
                float h2 = fmaxf(acc[n][2] + ba, 0.f);
                float h3 = fmaxf(acc[n][3] + bb, 0.f);
                uint32_t w01 = packbf(h1, h0), w23 = packbf(h3, h2);
                float r0 = h0 - __uint_as_float(w01 << 16);
                float r1 = h1 - __uint_as_float(w01 & 0xffff0000u);
                float r2 = h2 - __uint_as_float(w23 << 16);
                float r3 = h3 - __uint_as_float(w23 & 0xffff0000u);
                *(uint32_t*)(esm + E_XH + wrow * EROWB + col * 2)       = w01;
                *(uint32_t*)(esm + E_XH + (wrow + 8) * EROWB + col * 2) = w23;
                *(uint32_t*)(esm + E_XL + wrow * EROWB + col * 2)       = packbf(r1, r0);
                *(uint32_t*)(esm + E_XL + (wrow + 8) * EROWB + col * 2) = packbf(r3, r2);
            }
            #pragma unroll
            for (int it = 0; it < 2; it++) {
                int idx = tid + it * 256;
                int row = idx >> 3, c = idx & 7;
                cp16(sb + E_WH + row * EROWB + c * 16,
                     g_W2Thi + ((size_t)k * HID + row) * HID + c * 8);
                cp16(sb + E_WL + row * EROWB + c * 16,
                     g_W2Tlo + ((size_t)k * HID + row) * HID + c * 8);
            }
            CP_COMMIT();
            CP_WAIT(0);
            __syncthreads();
        } else if (mode == 1) {
            // final: write g_Khi/g_Klo + row norms
            const float* bp = b2 + k * HID;
            const size_t ga = (size_t)k * NH + row0 + wrow;
            float sA = 0.f, sB = 0.f;
            #pragma unroll
            for (int n = 0; n < 8; n++) {
                int col = n * 8 + tq * 2;
                float ba = __ldg(bp + col), bb = __ldg(bp + col + 1);
                float h0 = fmaxf(acc[n][0] + ba, 0.f);
                float h1 = fmaxf(acc[n][1] + bb, 0.f);
                float h2 = fmaxf(acc[n][2] + ba, 0.f);
                float h3 = fmaxf(acc[n][3] + bb, 0.f);
                sA += h0 * h0 + h1 * h1;
                sB += h2 * h2 + h3 * h3;
                uint32_t w01 = packbf(h1, h0), w23 = packbf(h3, h2);
                float r0 = h0 - __uint_as_float(w01 << 16);
                float r1 = h1 - __uint_as_float(w01 & 0xffff0000u);
                float r2 = h2 - __uint_as_float(w23 << 16);
                float r3 = h3 - __uint_as_float(w23 & 0xffff0000u);
                *(uint32_t*)((__nv_bfloat16*)g_Khi + ga * HID + col)       = w01;
                *(uint32_t*)((__nv_bfloat16*)g_Khi + (ga + 8) * HID + col) = w23;
                *(uint32_t*)((__nv_bfloat16*)g_Klo + ga * HID + col)       = packbf(r1, r0);
                *(uint32_t*)((__nv_bfloat16*)g_Klo + (ga + 8) * HID + col) = packbf(r3, r2);
            }
            sA += __shfl_xor_sync(0xffffffffu, sA, 1);
            sA += __shfl_xor_sync(0xffffffffu, sA, 2);
            sB += __shfl_xor_sync(0xffffffffu, sB, 1);
            sB += __shfl_xor_sync(0xffffffffu, sB, 2);
            if (tq == 0) {
                float mx = fmaxf(sqrtf(sA), sqrtf(sB));
                atomicMax((int*)&g_Kmax[k], __float_as_int(mx));
            }
        } else {
            // final: write fp32 g_enc_s (state encoder)
            const float* bp = b2 + k * HID;
            const size_t base = ((size_t)k * NB + row0 + wrow) * HID;
            #pragma unroll
            for (int n = 0; n < 8; n++) {
                int col = n * 8 + tq * 2;
                float ba = __ldg(bp + col), bb = __ldg(bp + col + 1);
                g_enc_s[base + col]               = fmaxf(acc[n][0] + ba, 0.f);
                g_enc_s[base + col + 1]           = fmaxf(acc[n][1] + bb, 0.f);
                g_enc_s[base + 8 * HID + col]     = fmaxf(acc[n][2] + ba, 0.f);
                g_enc_s[base + 8 * HID + col + 1] = fmaxf(acc[n][3] + bb, 0.f);
            }
        }
    }
}

// ---------------------------------------------------------------------------
// mma.sync flash attention. Grid (4, NK, NSPLIT), 512 thr.
// Single barrier per tile: CP_WAIT(0)+sync guards both data arrival and
// buffer reuse; prefetch of t+1 issued right after the sync.
// Split results accumulated directly via atomicAdd (shared m-hat).
// ---------------------------------------------------------------------------
__device__ __forceinline__ void load_tile(uint32_t sb, int k, int key0, int buf,
                                          int tid)
{
    const uint32_t kh = sb + (buf ? SM_KH1 : SM_KH0);
    const uint32_t kl = sb + (buf ? SM_KL1 : SM_KL0);
    const char* shi = (const char*)(g_Khi + ((size_t)k * NH + key0) * HID);
    const char* slo = (const char*)(g_Klo + ((size_t)k * NH + key0) * HID);
    #pragma unroll
    for (int it = 0; it < 2; it++) {
        int idx = tid + it * ATHR;              // 0..1023
        int row = idx >> 3, c = idx & 7;
        uint32_t doff = row * KROWB + c * 16;
        size_t goff = (size_t)row * 128 + c * 16;
        cp16(kh + doff, shi + goff);
        cp16(kl + doff, slo + goff);
    }
    const uint32_t vh = sb + (buf ? SM_VH1 : SM_VH0);
    const uint32_t vl = sb + (buf ? SM_VL1 : SM_VL0);
    const char* vhi = (const char*)g_VThi + (size_t)key0 * 2;
    const char* vlo = (const char*)g_VTlo + (size_t)key0 * 2;
    #pragma unroll
    for (int it = 0; it < 3; it++) {
        int idx = tid + it * ATHR;              // 0..1535, need 1280
        if (idx < 1280) {
            int a = idx >> 4, c = idx & 15;
            uint32_t doff = a * VROWB + c * 16;
            size_t goff = (size_t)a * NH * 2 + c * 16;
            cp16(vh + doff, vhi + goff);
            cp16(vl + doff, vlo + goff);
        }
    }
}

__global__ __launch_bounds__(ATHR, 1) void attn_kernel()
{
    extern __shared__ char smem[];
    const uint32_t sb = (uint32_t)__cvta_generic_to_shared(smem);
    const int tid  = threadIdx.x;
    const int warp = tid >> 5;
    const int lane = tid & 31;
    const int k    = blockIdx.y;
    const int sp   = blockIdx.z;
    const int q0   = blockIdx.x * MQ;
    const int kb0  = sp * KEYS_PER_CTA;

    const float* Qg = g_enc_s + ((size_t)k * NB + q0) * HID;
    float* MH = (float*)(smem + SM_MHAT);

    // m-hat per query row (fixed softmax bound)
    if (tid < MQ) {
        const float4* qr = (const float4*)(Qg + tid * HID);
        float ss = 0.f;
        #pragma unroll
        for (int i = 0; i < 16; i++) {
            float4 f = qr[i];
            ss += f.x * f.x + f.y * f.y + f.z * f.z + f.w * f.w;
        }
        MH[tid] = sqrtf(ss) * g_Kmax[k];
    }

    // stage Q: hi into SM_QHI (aliases K buf0, 256 rows), lo into SM_QLO
    {
        int row = tid >> 1, half = tid & 1;
        const float* qr = Qg + row * HID + half * 32;
        char* dh = smem + SM_QHI + row * KROWB + half * 64;
        char* dl = smem + SM_QLO + row * KROWB + half * 64;
        #pragma unroll
        for (int i = 0; i < 8; i++) {
            float4 f = *(const float4*)(qr + i * 4);
            uint32_t h0 = packbf(f.y, f.x);
            uint32_t h1 = packbf(f.w, f.z);
            float r0 = f.x - __uint_as_float(h0 << 16);
            float r1 = f.y - __uint_as_float(h0 & 0xffff0000u);
            float r2 = f.z - __uint_as_float(h1 << 16);
            float r3 = f.w - __uint_as_float(h1 & 0xffff0000u);
            *(uint32_t*)(dh + i * 8)     = h0;
            *(uint32_t*)(dh + i * 8 + 4) = h1;
            *(uint32_t*)(dl + i * 8)     = packbf(r1, r0);
            *(uint32_t*)(dl + i * 8 + 4) = packbf(r3, r2);
        }
    }
    __syncthreads();

    // Q-hi fragments to registers (Q-lo stays resident in SM_QLO)
    uint32_t qh[4][4];
    const uint32_t qro = (16 * warp + (lane & 15)) * KROWB;
    const uint32_t qsel = ((lane >> 4) & 1) * 8;
    #pragma unroll
    for (int kk = 0; kk < 4; kk++)
        ldsm4(qh[kk], sb + SM_QHI + qro + (kk * 16 + qsel) * 2);
    const float mh0 = MH[16 * warp + (lane >> 2)];
    const float mh1 = MH[16 * warp + (lane >> 2) + 8];
    __syncthreads();   // Q-hi staging area now free for K tiles

    load_tile(sb, k, kb0, 0, tid);
    CP_COMMIT();

    float oacc[10][4];
    #pragma unroll
    for (int ab = 0; ab < 10; ab++)
        #pragma unroll
        for (int e = 0; e < 4; e++) oacc[ab][e] = 0.f;
    float lacc0 = 0.f, lacc1 = 0.f;

    const uint32_t lr8 = (lane & 7), lc8 = ((lane >> 3) & 3);
    const int hswap = (warp >> 3) & 1;   // warps 8-15 reverse half order

    for (int t = 0; t < TILES; t++) {
        CP_WAIT(0);          // tile t's data complete
        __syncthreads();     // visible to all; all warps done with buffer t-1

        if (t + 1 < TILES) {
            load_tile(sb, k, kb0 + (t + 1) * KT, (t + 1) & 1, tid);
            CP_COMMIT();
        }

        const uint32_t KH = sb + ((t & 1) ? SM_KH1 : SM_KH0);
        const uint32_t KL = sb + ((t & 1) ? SM_KL1 : SM_KL0);
        const uint32_t VH = sb + ((t & 1) ? SM_VH1 : SM_VH0);
        const uint32_t VL = sb + ((t & 1) ? SM_VL1 : SM_VL0);

        #pragma unroll
        for (int hfi = 0; hfi < 2; hfi++) {
            const int hf = hswap ? (1 - hfi) : hfi;
            // ---- scores for 64-key half: S = QhiKhi + QloKhi + QhiKlo ----
            float sacc[8][4];
            #pragma unroll
            for (int nb = 0; nb < 8; nb++)
                #pragma unroll
                for (int e = 0; e < 4; e++) sacc[nb][e] = 0.f;

            #pragma unroll
            for (int dp = 0; dp < 2; dp++) {
                uint32_t qlA[4], qlB[4];
                ldsm4(qlA, sb + SM_QLO + qro + ((2 * dp) * 16 + qsel) * 2);
                ldsm4(qlB, sb + SM_QLO + qro + ((2 * dp + 1) * 16 + qsel) * 2);
                const uint32_t co = (dp * 32 + lc8 * 8) * 2;
                const int k0 = 2 * dp, k1 = 2 * dp + 1;
                #pragma unroll
                for (int nb2 = 0; nb2 < 4; nb2++) {
                    const int n0 = hf * 8 + 2 * nb2, n1 = n0 + 1;
                    const int l0 = 2 * nb2, l1 = l0 + 1;
                    uint32_t bh0[4], bl0[4], bh1[4], bl1[4];
                    ldsm4(bh0, KH + (n0 * 8 + lr8) * KROWB + co);
                    ldsm4(bh1, KH + (n1 * 8 + lr8) * KROWB + co);
                    ldsm4(bl0, KL + (n0 * 8 + lr8) * KROWB + co);
                    ldsm4(bl1, KL + (n1 * 8 + lr8) * KROWB + co);
                    mma16816(sacc[l0], qh[k0], bh0[0], bh0[1]);
                    mma16816(sacc[l1], qh[k0], bh1[0], bh1[1]);
                    mma16816(sacc[l0], qh[k1], bh0[2], bh0[3]);
                    mma16816(sacc[l1], qh[k1], bh1[2], bh1[3]);
                    mma16816(sacc[l0], qlA, bh0[0], bh0[1]);
                    mma16816(sacc[l1], qlA, bh1[0], bh1[1]);
                    mma16816(sacc[l0], qlB, bh0[2], bh0[3]);
                    mma16816(sacc[l1], qlB, bh1[2], bh1[3]);
                    mma16816(sacc[l0], qh[k0], bl0[0], bl0[1]);
                    mma16816(sacc[l1], qh[k0], bl1[0], bl1[1]);
                    mma16816(sacc[l0], qh[k1], bl0[2], bl0[3]);
                    mma16816(sacc[l1], qh[k1], bl1[2], bl1[3]);
                }
            }

            // ---- softmax with fixed bound ----
            #pragma unroll
            for (int nb = 0; nb < 8; nb++) {
                float p0 = __expf(sacc[nb][0] - mh0);
                float p1 = __expf(sacc[nb][1] - mh0);
                float p2 = __expf(sacc[nb][2] - mh1);
                float p3 = __expf(sacc[nb][3] - mh1);
                lacc0 += p0 + p1;
                lacc1 += p2 + p3;
                sacc[nb][0] = p0; sacc[nb][1] = p1;
                sacc[nb][2] = p2; sacc[nb][3] = p3;
            }

            // ---- PV over this key half: O += PhiVhi + PloVhi + PhiVlo ----
            #pragma unroll
            for (int jp = 0; jp < 2; jp++) {
                uint32_t ah[2][4], al[2][4];
                #pragma unroll
                for (int m = 0; m < 2; m++) {
                    const int nA = 4 * jp + 2 * m;
                    #pragma unroll
                    for (int h = 0; h < 2; h++) {
                        float c0 = sacc[nA + h][0], c1 = sacc[nA + h][1];
                        float c2 = sacc[nA + h][2], c3 = sacc[nA + h][3];
                        uint32_t h01 = packbf(c1, c0);
                        uint32_t h23 = packbf(c3, c2);
                        ah[m][2 * h]     = h01;
                        ah[m][2 * h + 1] = h23;
                        float r0 = c0 - __uint_as_float(h01 << 16);
                        float r1 = c1 - __uint_as_float(h01 & 0xffff0000u);
                        float r2 = c2 - __uint_as_float(h23 << 16);
                        float r3 = c3 - __uint_as_float(h23 & 0xffff0000u);
                        al[m][2 * h]     = packbf(r1, r0);
                        al[m][2 * h + 1] = packbf(r3, r2);
                    }
                }
                const uint32_t co = ((hf * 2 + jp) * 32 + lc8 * 8) * 2;
                #pragma unroll
                for (int ab2 = 0; ab2 < 5; ab2++) {
                    const int a0 = 2 * ab2, a1 = a0 + 1;
                    uint32_t vh0[4], vh1[4], vl0[4], vl1[4];
                    ldsm4(vh0, VH + (a0 * 8 + lr8) * VROWB + co);
                    ldsm4(vh1, VH + (a1 * 8 + lr8) * VROWB + co);
                    mma16816(oacc[a0], ah[0], vh0[0], vh0[1]);
                    mma16816(oacc[a1], ah[0], vh1[0], vh1[1]);
                    mma16816(oacc[a0], ah[1], vh0[2], vh0[3]);
                    mma16816(oacc[a1], ah[1], vh1[2], vh1[3]);
                    mma16816(oacc[a0], al[0], vh0[0], vh0[1]);
                    mma16816(oacc[a1], al[0], vh1[0], vh1[1]);
                    mma16816(oacc[a0], al[1], vh0[2], vh0[3]);
                    mma16816(oacc[a1], al[1], vh1[2], vh1[3]);
                    ldsm4(vl0, VL + (a0 * 8 + lr8) * VROWB + co);
                    ldsm4(vl1, VL + (a1 * 8 + lr8) * VROWB + co);
                    mma16816(oacc[a0], ah[0], vl0[0], vl0[1]);
                    mma16816(oacc[a1], ah[0], vl1[0], vl1[1]);
                    mma16816(oacc[a0], ah[1], vl0[2], vl0[3]);
                    mma16816(oacc[a1], ah[1], vl1[2], vl1[3]);
                }
            }
        }
    }

    // ---- epilogue: atomic-accumulate O + l across splits ----
    const int r  = lane >> 2, tq = lane & 3;
    const int qrow0 = q0 + 16 * warp + r;
    const int qrow1 = qrow0 + 8;
    float* Ob = g_Oacc + ((size_t)k * NB) * GA;
    #pragma unroll
    for (int ab = 0; ab < 10; ab++) {
        const int col = ab * 8 + tq * 2;
        atomicAdd(&Ob[(size_t)qrow0 * GA + col],     oacc[ab][0]);
        atomicAdd(&Ob[(size_t)qrow0 * GA + col + 1], oacc[ab][1]);
        atomicAdd(&Ob[(size_t)qrow1 * GA + col],     oacc[ab][2]);
        atomicAdd(&Ob[(size_t)qrow1 * GA + col + 1], oacc[ab][3]);
    }
    lacc0 += __shfl_xor_sync(0xffffffffu, lacc0, 1);
    lacc0 += __shfl_xor_sync(0xffffffffu, lacc0, 2);
    lacc1 += __shfl_xor_sync(0xffffffffu, lacc1, 1);
    lacc1 += __shfl_xor_sync(0xffffffffu, lacc1, 2);
    if (tq == 0) {
        atomicAdd(&g_lacc[k * NB + qrow0], lacc0);
        atomicAdd(&g_lacc[k * NB + qrow1], lacc1);
    }
    (void)sp;
}

// ---------------------------------------------------------------------------
// Merge: normalize accumulated O, k-combine with softmaxed assignment.
// ---------------------------------------------------------------------------
__global__ __launch_bounds__(256) void merge_kernel(
    const float* __restrict__ assign, float* __restrict__ out)
{
    int idx = blockIdx.x * 256 + threadIdx.x;
    if (idx >= NB * GA) return;
    int b  = idx / GA;
    int ga = idx - b * GA;
    int g  = ga >> 3;

    float aw[NK], mxw = -CUDART_INF_F;
    #pragma unroll
    for (int k = 0; k < NK; k++) {
        aw[k] = __ldg(assign + g * NK + k);
        mxw = fmaxf(mxw, aw[k]);
    }
    float wsum = 0.f;
    #pragma unroll
    for (int k = 0; k < NK; k++) { aw[k] = __expf(aw[k] - mxw); wsum += aw[k]; }
    float winv = 1.f / wsum;

    float acc = 0.f;
    #pragma unroll
    for (int k = 0; k < NK; k++)
        acc += aw[k] * (g_Oacc[((size_t)k * NB + b) * GA + ga] /
                        g_lacc[k * NB + b]);
    out[idx] = acc * winv;
}

// ---------------------------------------------------------------------------
extern "C" void kernel_launch(void* const* d_in, const int* in_sizes, int n_in,
                              void* d_out, int out_size)
{
    (void)in_sizes; (void)n_in; (void)out_size;
    const float* state  = (const float*)d_in[0];
    const float* hist   = (const float*)d_in[1];
    const float* jah    = (const float*)d_in[2];
    const float* W0 = (const float*)d_in[3];
    const float* b0 = (const float*)d_in[4];
    const float* W1 = (const float*)d_in[5];
    const float* b1 = (const float*)d_in[6];
    const float* W2 = (const float*)d_in[7];
    const float* b2 = (const float*)d_in[8];
    const float* assign = (const float*)d_in[9];
    float* out = (float*)d_out;

    prep_kernel<<<416, 256>>>(jah, W0, W1, W2);

    cudaFuncSetAttribute(encoder_k_kernel,
                         cudaFuncAttributeMaxDynamicSharedMemorySize, E_TOTAL);
    encoder_k_kernel<<<dim3(136, NK), 256, E_TOTAL>>>(hist, state, b0, b1, b2);

    cudaFuncSetAttribute(attn_kernel,
                         cudaFuncAttributeMaxDynamicSharedMemorySize, SM_TOTAL);
    attn_kernel<<<dim3(NB / MQ, NK, NSPLIT), ATHR, SM_TOTAL>>>();

    merge_kernel<<<(NB * GA + 255) / 256, 256>>>(assign, out);
}